// round 8
// baseline (speedup 1.0000x reference)
#include <cuda_runtime.h>
#include <cuda_fp16.h>
#include <cstdint>

#define Bb 4
#define Tt 1024
#define Ss 128
#define Cc 1024
#define NLAYER 8
#define VOC 4096
#define Lseq 2048

#define N_BLC (Bb*Lseq*Cc)
#define N_HF  (Bb*Tt*Cc)

__device__ float g_f32[2*N_BLC + N_HF];       // X, X2, HF
__device__ float g_bqkv[NLAYER*3072];         // fused qkv bias
__device__ __half g_hp[198311936];            // all fp16 planes (~397MB)

// ---------------- helpers ----------------
__device__ __forceinline__ void ldsm4(uint32_t r[4], const __half* p) {
    uint32_t a = (uint32_t)__cvta_generic_to_shared(p);
    asm volatile("ldmatrix.sync.aligned.m8n8.x4.shared.b16 {%0,%1,%2,%3}, [%4];"
        : "=r"(r[0]), "=r"(r[1]), "=r"(r[2]), "=r"(r[3]) : "r"(a));
}
__device__ __forceinline__ void ldsm4t(uint32_t r[4], const __half* p) {
    uint32_t a = (uint32_t)__cvta_generic_to_shared(p);
    asm volatile("ldmatrix.sync.aligned.m8n8.x4.trans.shared.b16 {%0,%1,%2,%3}, [%4];"
        : "=r"(r[0]), "=r"(r[1]), "=r"(r[2]), "=r"(r[3]) : "r"(a));
}
__device__ __forceinline__ void mma_f16(float c[4], const uint32_t a[4], const uint32_t b[2]) {
    asm volatile("mma.sync.aligned.m16n8k16.row.col.f32.f16.f16.f32 "
        "{%0,%1,%2,%3}, {%4,%5,%6,%7}, {%8,%9}, {%0,%1,%2,%3};"
        : "+f"(c[0]), "+f"(c[1]), "+f"(c[2]), "+f"(c[3])
        : "r"(a[0]), "r"(a[1]), "r"(a[2]), "r"(a[3]), "r"(b[0]), "r"(b[1]));
}
__device__ __forceinline__ void cpa16(__half* dst, const __half* src) {
    uint32_t d = (uint32_t)__cvta_generic_to_shared(dst);
    asm volatile("cp.async.cg.shared.global [%0], [%1], 16;" :: "r"(d), "l"(src));
}
__device__ __forceinline__ void split1h(float v, __half& h, __half& l) {
    h = __float2half_rn(v);
    l = __float2half_rn(v - __half2float(h));
}
__device__ __forceinline__ float fast_exp(float x) {
    x = fmaxf(x, -80.f);
    float y = x * 1.44269504088896f;
    float t = y + 12582912.f;
    int ni = __float_as_int(t) - 0x4B400000;
    float f = y - (t - 12582912.f);
    float p = 1.33335581e-3f;
    p = fmaf(p, f, 9.61812910e-3f);
    p = fmaf(p, f, 5.55041087e-2f);
    p = fmaf(p, f, 2.40226507e-1f);
    p = fmaf(p, f, 6.93147180e-1f);
    p = fmaf(p, f, 1.0f);
    return p * __int_as_float((ni + 127) << 23);
}

// ---------------- GEMM: out = act((Ah+Al)@W16^T + bias)(+res) ----------------
// CTA tile 128x256 (BK=32), 8 warps (2x4) of 64x64. 3-stage cp.async.
// A planes [M,K] fp16 hi/lo; W PRE-TRANSPOSED [N,K] fp16. 2 MMAs per frag.
// PL: 0=fp32 out, 1=1 plane, 2=2 planes.
#define ST_HALVES 20480   // per stage: Ah 5120 + Al 5120 + W 10240 halves
template<int ACT, bool HASBIAS, bool HASRES, int PL>
__global__ __launch_bounds__(256, 1) void gemm_hk(
    const __half* __restrict__ Ah, const __half* __restrict__ Al,
    const __half* __restrict__ Wh,
    const float* __restrict__ bias, const float* __restrict__ res,
    float* __restrict__ out, __half* __restrict__ outH, __half* __restrict__ outL,
    int M, int N, int K)
{
    extern __shared__ __half sm[];
    int tid = threadIdx.x, lane = tid & 31, warp = tid >> 5;
    int bm = blockIdx.y * 128, bn = blockIdx.x * 256;
    int wr = (warp >> 2) * 64;        // warp row offset (0 or 64)
    int wc = (warp & 3) * 64;         // warp col offset (0..192)

    float acc[4][8][4];
    #pragma unroll
    for (int i = 0; i < 4; i++)
        #pragma unroll
        for (int j = 0; j < 8; j++)
            #pragma unroll
            for (int q = 0; q < 4; q++) acc[i][j][q] = 0.f;

    int niter = K >> 5;

    // 2048 16B-chunks per stage: A planes 1024 (2x128x4), W 1024 (256x4); 8/thread
    #define ISSUE(ST, K0) do {                                                  \
        int _k0 = (K0);                                                         \
        _Pragma("unroll")                                                       \
        for (int _i = 0; _i < 8; _i++) {                                        \
            int _id = tid + (_i << 8);                                          \
            const __half* _src;                                                 \
            __half* _dst;                                                       \
            if (_id < 1024) {                                                   \
                int _pl = _id >> 9;                                             \
                int _r = (_id >> 2) & 127;                                      \
                int _c = (_id & 3) << 3;                                        \
                _src = (_pl ? Al : Ah) + (size_t)(bm + _r) * K + _k0 + _c;      \
                _dst = sm + (ST)*ST_HALVES + _pl*5120 + _r*40 + _c;             \
            } else {                                                            \
                int _r = (_id >> 2) & 255;                                      \
                int _c = (_id & 3) << 3;                                        \
                _src = Wh + (size_t)(bn + _r) * K + _k0 + _c;                   \
                _dst = sm + (ST)*ST_HALVES + 10240 + _r*40 + _c;                \
            }                                                                   \
            cpa16(_dst, _src);                                                  \
        }                                                                       \
        asm volatile("cp.async.commit_group;" ::: "memory");                    \
    } while (0)

    ISSUE(0, 0);
    if (niter > 1) ISSUE(1, 32);
    for (int it = 0; it < niter; ++it) {
        if (it + 1 < niter) {
            asm volatile("cp.async.wait_group 1;" ::: "memory");
        } else {
            asm volatile("cp.async.wait_group 0;" ::: "memory");
        }
        __syncthreads();
        if (it + 2 < niter) ISSUE((it + 2) % 3, (it + 2) << 5);

        int st = it % 3;
        const __half* AshH = sm + st*ST_HALVES;
        const __half* AshL = AshH + 5120;
        const __half* BshW = AshH + 10240;

        #pragma unroll
        for (int ks = 0; ks < 2; ks++) {
            uint32_t aH[4][4], aL[4][4];
            #pragma unroll
            for (int mi = 0; mi < 4; mi++) {
                int row = wr + mi*16 + (lane & 15);
                int col = ks*16 + ((lane >> 4) << 3);
                ldsm4(aH[mi], &AshH[row*40 + col]);
                ldsm4(aL[mi], &AshL[row*40 + col]);
            }
            uint32_t bW[8][2];
            #pragma unroll
            for (int pi = 0; pi < 4; pi++) {
                int nr = wc + pi*16 + ((lane >> 4) << 3) + (lane & 7);
                int kc = ks*16 + (((lane >> 3) & 1) << 3);
                uint32_t t[4];
                ldsm4(t, &BshW[nr*40 + kc]);
                bW[2*pi][0] = t[0]; bW[2*pi][1] = t[1];
                bW[2*pi+1][0] = t[2]; bW[2*pi+1][1] = t[3];
            }
            #pragma unroll
            for (int mi = 0; mi < 4; mi++)
                #pragma unroll
                for (int nj = 0; nj < 8; nj++) {
                    mma_f16(acc[mi][nj], aH[mi], bW[nj]);
                    mma_f16(acc[mi][nj], aL[mi], bW[nj]);
                }
        }
    }
    #undef ISSUE

    int g = lane >> 2, tg = lane & 3;
    #pragma unroll
    for (int mi = 0; mi < 4; mi++)
        #pragma unroll
        for (int nj = 0; nj < 8; nj++) {
            int r0 = bm + wr + mi*16 + g;
            int c0 = bn + wc + nj*8 + tg*2;
            float v[4];
            #pragma unroll
            for (int q = 0; q < 4; q++) {
                float x = acc[mi][nj][q];
                if (HASBIAS) x += bias[c0 + (q & 1)];
                if (ACT == 1) x = tanhf(x);
                else if (ACT == 2) x = 0.5f * x * (1.0f + erff(x * 0.70710678f));
                v[q] = x;
            }
            if (PL == 2) {
                #pragma unroll
                for (int h2 = 0; h2 < 2; h2++) {
                    int r = r0 + h2*8;
                    __half h0, h1, l0, l1;
                    split1h(v[2*h2], h0, l0);
                    split1h(v[2*h2+1], h1, l1);
                    __half2 hh; hh.x = h0; hh.y = h1;
                    __half2 ll; ll.x = l0; ll.y = l1;
                    *(__half2*)&outH[(size_t)r*N + c0] = hh;
                    *(__half2*)&outL[(size_t)r*N + c0] = ll;
                }
            } else if (PL == 1) {
                #pragma unroll
                for (int h2 = 0; h2 < 2; h2++) {
                    int r = r0 + h2*8;
                    __half2 hh;
                    hh.x = __float2half_rn(v[2*h2]);
                    hh.y = __float2half_rn(v[2*h2+1]);
                    *(__half2*)&outH[(size_t)r*N + c0] = hh;
                }
            } else {
                #pragma unroll
                for (int q = 0; q < 4; q++) {
                    int r = r0 + (q >> 1) * 8, c = c0 + (q & 1);
                    float x = v[q];
                    if (HASRES) x += res[(size_t)r * N + c];
                    out[(size_t)r * N + c] = x;
                }
            }
        }
}

// ---------------- LayerNorm -> 2 fp16 planes ----------------
__global__ __launch_bounds__(256) void ln_kernel(
    const float* __restrict__ x, const float* __restrict__ g,
    const float* __restrict__ b, __half* __restrict__ oh,
    __half* __restrict__ ol, int gather)
{
    int row = blockIdx.x;
    int src = gather ? ((row / Tt) * Lseq + 2 * (row % Tt) + 1) : row;
    float4 v = ((const float4*)(x + (size_t)src * Cc))[threadIdx.x];
    float s = v.x + v.y + v.z + v.w;
    float q = v.x*v.x + v.y*v.y + v.z*v.z + v.w*v.w;
    #pragma unroll
    for (int o = 16; o; o >>= 1) {
        s += __shfl_xor_sync(0xffffffffu, s, o);
        q += __shfl_xor_sync(0xffffffffu, q, o);
    }
    __shared__ float ss[8], sq[8];
    int w = threadIdx.x >> 5;
    if ((threadIdx.x & 31) == 0) { ss[w] = s; sq[w] = q; }
    __syncthreads();
    s = 0.f; q = 0.f;
    #pragma unroll
    for (int i = 0; i < 8; i++) { s += ss[i]; q += sq[i]; }
    float mean = s * (1.0f / Cc);
    float rstd = rsqrtf(q * (1.0f / Cc) - mean * mean + 1e-5f);
    float4 gv = ((const float4*)g)[threadIdx.x];
    float4 bv = ((const float4*)b)[threadIdx.x];
    float o4[4];
    o4[0] = (v.x - mean) * rstd * gv.x + bv.x;
    o4[1] = (v.y - mean) * rstd * gv.y + bv.y;
    o4[2] = (v.z - mean) * rstd * gv.z + bv.z;
    o4[3] = (v.w - mean) * rstd * gv.w + bv.w;
    size_t base = (size_t)row * Cc + threadIdx.x * 4;
    __half h[4], l[4];
    #pragma unroll
    for (int e = 0; e < 4; e++) split1h(o4[e], h[e], l[e]);
    __half2 p;
    p.x=h[0]; p.y=h[1]; *(__half2*)&oh[base]   = p;
    p.x=h[2]; p.y=h[3]; *(__half2*)&oh[base+2] = p;
    p.x=l[0]; p.y=l[1]; *(__half2*)&ol[base]   = p;
    p.x=l[2]; p.y=l[3]; *(__half2*)&ol[base+2] = p;
}

// ---------------- token assembly ----------------
__global__ __launch_bounds__(256) void assemble_kernel(
    const float* __restrict__ SE, const int* __restrict__ actions,
    const int* __restrict__ tsteps, const float* __restrict__ act_table,
    const float* __restrict__ pos_emb, const float* __restrict__ gpe_table,
    float* __restrict__ x)
{
    int bt = blockIdx.x;
    int b = bt / Tt, t = bt % Tt;
    int a = actions[bt];
    int ts = tsteps[bt];
    size_t row0 = (size_t)(b * Lseq + 2*t) * Cc;
    for (int c = threadIdx.x; c < Cc; c += 256) {
        float gp = gpe_table[(size_t)ts * Cc + c];
        x[row0 + c]      = SE[(size_t)bt * Cc + c] + gp + pos_emb[(size_t)(2*t) * Cc + c];
        x[row0 + Cc + c] = tanhf(act_table[(size_t)a * Cc + c]) + gp + pos_emb[(size_t)(2*t+1) * Cc + c];
    }
}

// ---------------- MMA flash attention (fp16 2-term), fused QKV input ----------------
__global__ __launch_bounds__(128) void attn_kernel(
    const __half* __restrict__ QKVH, const __half* __restrict__ QKVL,
    __half* __restrict__ OutH, __half* __restrict__ OutL)
{
    extern __shared__ __half smb[];
    __half* sQH = smb;
    __half* sQL = smb + 4608;
    __half* sKH = smb + 2*4608;
    __half* sVH = smb + 3*4608;

    int tid = threadIdx.x, lane = tid & 31, wid = tid >> 5;
    int b = blockIdx.y >> 4, h = blockIdx.y & 15;
    int q0 = blockIdx.x * 64;
    size_t gbase = (size_t)b * Lseq * 3072 + h * 64;

    #pragma unroll
    for (int i = 0; i < 8; i++) {
        int id = tid + i*128;
        int pl = id >> 9;
        int r = (id >> 3) & 63;
        int c = (id & 7) << 3;
        cpa16((pl ? sQL : sQH) + r*72 + c,
              (pl ? QKVL : QKVH) + gbase + (size_t)(q0 + r)*3072 + c);
    }
    asm volatile("cp.async.commit_group;" ::: "memory");

    float m0 = -1e30f, m1 = -1e30f, lsum0 = 0.f, lsum1 = 0.f;
    float O[8][4];
    #pragma unroll
    for (int f = 0; f < 8; f++)
        #pragma unroll
        for (int q = 0; q < 4; q++) O[f][q] = 0.f;

    int g = lane >> 2, tg = lane & 3;
    int wq = wid * 16;
    int row0 = q0 + wq + g, row1 = row0 + 8;
    int ntiles = blockIdx.x + 1;

    for (int kt = 0; kt < ntiles; kt++) {
        int j0 = kt * 64;
        #pragma unroll
        for (int i = 0; i < 8; i++) {
            int id = tid + i*128;
            int pl = id >> 9;                 // 0: K, 1: V
            int r = (id >> 3) & 63;
            int c = (id & 7) << 3;
            const __half* src = QKVH + gbase + (size_t)(j0 + r)*3072 + (pl ? 2048 : 1024) + c;
            __half* dst = (pl ? sVH : sKH) + r*72 + c;
            cpa16(dst, src);
        }
        asm volatile("cp.async.commit_group;" ::: "memory");
        asm volatile("cp.async.wait_group 0;" ::: "memory");
        __syncthreads();

        float S[8][4];
        #pragma unroll
        for (int f = 0; f < 8; f++)
            #pragma unroll
            for (int q = 0; q < 4; q++) S[f][q] = 0.f;

        #pragma unroll
        for (int ks = 0; ks < 4; ks++) {
            int arow = wq + (lane & 15);
            int acol = ks*16 + ((lane >> 4) << 3);
            uint32_t aH[4], aL[4];
            ldsm4(aH, sQH + arow*72 + acol);
            ldsm4(aL, sQL + arow*72 + acol);
            #pragma unroll
            for (int nb = 0; nb < 4; nb++) {
                int nr = nb*16 + ((lane >> 4) << 3) + (lane & 7);
                int kc = ks*16 + (((lane >> 3) & 1) << 3);
                uint32_t tK[4];
                ldsm4(tK, sKH + nr*72 + kc);
                uint32_t b0[2] = {tK[0], tK[1]}, b1[2] = {tK[2], tK[3]};
                mma_f16(S[2*nb],   aH, b0);
                mma_f16(S[2*nb],   aL, b0);
                mma_f16(S[2*nb+1], aH, b1);
                mma_f16(S[2*nb+1], aL, b1);
            }
        }

        #pragma unroll
        for (int f = 0; f < 8; f++) {
            int kcol = j0 + f*8 + tg*2;
            float v0 = S[f][0]*0.125f; if (kcol   > row0) v0 = -1e30f;
            float v1 = S[f][1]*0.125f; if (kcol+1 > row0) v1 = -1e30f;
            float v2 = S[f][2]*0.125f; if (kcol   > row1) v2 = -1e30f;
            float v3 = S[f][3]*0.125f; if (kcol+1 > row1) v3 = -1e30f;
            S[f][0] = v0; S[f][1] = v1; S[f][2] = v2; S[f][3] = v3;
        }
        float r0m = -1e30f, r1m = -1e30f;
        #pragma unroll
        for (int f = 0; f < 8; f++) {
            r0m = fmaxf(r0m, fmaxf(S[f][0], S[f][1]));
            r1m = fmaxf(r1m, fmaxf(S[f][2], S[f][3]));
        }
        r0m = fmaxf(r0m, __shfl_xor_sync(0xffffffffu, r0m, 1));
        r0m = fmaxf(r0m, __shfl_xor_sync(0xffffffffu, r0m, 2));
        r1m = fmaxf(r1m, __shfl_xor_sync(0xffffffffu, r1m, 1));
        r1m = fmaxf(r1m, __shfl_xor_sync(0xffffffffu, r1m, 2));
        float mn0 = fmaxf(m0, r0m), mn1 = fmaxf(m1, r1m);
        float a0 = fast_exp(m0 - mn0), a1 = fast_exp(m1 - mn1);
        m0 = mn0; m1 = mn1;

        float s0 = 0.f, s1 = 0.f;
        #pragma unroll
        for (int f = 0; f < 8; f++) {
            float p0 = fast_exp(S[f][0] - mn0);
            float p1 = fast_exp(S[f][1] - mn0);
            float p2 = fast_exp(S[f][2] - mn1);
            float p3 = fast_exp(S[f][3] - mn1);
            S[f][0] = p0; S[f][1] = p1; S[f][2] = p2; S[f][3] = p3;
            s0 += p0 + p1; s1 += p2 + p3;
        }
        s0 += __shfl_xor_sync(0xffffffffu, s0, 1);
        s0 += __shfl_xor_sync(0xffffffffu, s0, 2);
        s1 += __shfl_xor_sync(0xffffffffu, s1, 1);
        s1 += __shfl_xor_sync(0xffffffffu, s1, 2);
        lsum0 = lsum0 * a0 + s0;
        lsum1 = lsum1 * a1 + s1;
        #pragma unroll
        for (int f = 0; f < 8; f++) {
            O[f][0] *= a0; O[f][1] *= a0;
            O[f][2] *= a1; O[f][3] *= a1;
        }

        #pragma unroll
        for (int ks2 = 0; ks2 < 4; ks2++) {
            uint32_t pH[4], pL[4];
            #pragma unroll
            for (int hf = 0; hf < 2; hf++) {
                int f = 2*ks2 + hf;
                __half h0,h1,h2,h3,l0,l1,l2,l3;
                split1h(S[f][0], h0, l0); split1h(S[f][1], h1, l1);
                split1h(S[f][2], h2, l2); split1h(S[f][3], h3, l3);
                __half2 t;
                t.x=h0; t.y=h1; pH[hf*2+0] = *(uint32_t*)&t;
                t.x=h2; t.y=h3; pH[hf*2+1] = *(uint32_t*)&t;
                t.x=l0; t.y=l1; pL[hf*2+0] = *(uint32_t*)&t;
                t.x=l2; t.y=l3; pL[hf*2+1] = *(uint32_t*)&t;
            }
            int vrow = ks2*16 + (lane & 15);
            #pragma unroll
            for (int nb = 0; nb < 4; nb++) {
                int vcol = nb*16 + ((lane >> 4) << 3);
                uint32_t tV[4];
                ldsm4t(tV, sVH + vrow*72 + vcol);
                uint32_t b0[2] = {tV[0], tV[1]}, b1[2] = {tV[2], tV[3]};
                mma_f16(O[2*nb],   pH, b0);
                mma_f16(O[2*nb],   pL, b0);
                mma_f16(O[2*nb+1], pH, b1);
                mma_f16(O[2*nb+1], pL, b1);
            }
        }
        __syncthreads();
    }

    float rl0 = 1.f / lsum0, rl1 = 1.f / lsum1;
    size_t t0 = (size_t)(b*Lseq + row0), t1 = (size_t)(b*Lseq + row1);
    #pragma unroll
    for (int f = 0; f < 8; f++) {
        int gcol = h*64 + f*8 + tg*2;
        __half h0,h1,l0,l1;
        split1h(O[f][0]*rl0, h0, l0);
        split1h(O[f][1]*rl0, h1, l1);
        __half2 ph, plo;
        ph.x=h0; ph.y=h1; plo.x=l0; plo.y=l1;
        *(__half2*)&OutH[t0*Cc + gcol] = ph;
        *(__half2*)&OutL[t0*Cc + gcol] = plo;
        split1h(O[f][2]*rl1, h0, l0);
        split1h(O[f][3]*rl1, h1, l1);
        ph.x=h0; ph.y=h1; plo.x=l0; plo.y=l1;
        *(__half2*)&OutH[t1*Cc + gcol] = ph;
        *(__half2*)&OutL[t1*Cc + gcol] = plo;
    }
}

// ---------------- batched weight transpose + fp16 ----------------
__global__ __launch_bounds__(256) void wsplit_kernel(
    const float* __restrict__ W, __half* __restrict__ Wh, int K, int N,
    size_t inStride, size_t outStride)
{
    const float* Wz = W + (size_t)blockIdx.z * inStride;
    __half* Whz = Wh + (size_t)blockIdx.z * outStride;
    __shared__ float tile[32][33];
    int k0 = blockIdx.y * 32, n0 = blockIdx.x * 32;
    int tx = threadIdx.x & 31, ty = threadIdx.x >> 5;
    #pragma unroll
    for (int r = ty; r < 32; r += 8)
        tile[r][tx] = Wz[(size_t)(k0 + r) * N + n0 + tx];
    __syncthreads();
    #pragma unroll
    for (int r = ty; r < 32; r += 8)
        Whz[(size_t)(n0 + r) * K + k0 + tx] = __float2half_rn(tile[tx][r]);
}

// ---------------- fused QKV bias concat ----------------
__global__ __launch_bounds__(256) void bcat_kernel(
    const float* __restrict__ bq, const float* __restrict__ bk,
    const float* __restrict__ bv, float* __restrict__ outb)
{
    int i = blockIdx.x * 256 + threadIdx.x;
    if (i < NLAYER * 3072) {
        int lyr = i / 3072, c = i % 3072;
        float v = (c < 1024) ? bq[lyr*1024 + c]
                : (c < 2048) ? bk[lyr*1024 + c - 1024]
                             : bv[lyr*1024 + c - 2048];
        outb[i] = v;
    }
}

// ---------------- elementwise 2-plane split (states) ----------------
__global__ __launch_bounds__(256) void esplit_kernel(
    const float* __restrict__ x, __half* __restrict__ h,
    __half* __restrict__ l, int n)
{
    int i = (blockIdx.x * 256 + threadIdx.x) * 4;
    if (i < n) {
        float4 v = *(const float4*)&x[i];
        float a[4] = {v.x, v.y, v.z, v.w};
        __half hh[4], ll[4];
        #pragma unroll
        for (int e = 0; e < 4; e++) split1h(a[e], hh[e], ll[e]);
        __half2 p;
        p.x=hh[0]; p.y=hh[1]; *(__half2*)&h[i]   = p;
        p.x=hh[2]; p.y=hh[3]; *(__half2*)&h[i+2] = p;
        p.x=ll[0]; p.y=ll[1]; *(__half2*)&l[i]   = p;
        p.x=ll[2]; p.y=ll[3]; *(__half2*)&l[i+2] = p;
    }
}

// ---------------- launcher ----------------
extern "C" void kernel_launch(void* const* d_in, const int* in_sizes, int n_in,
                              void* d_out, int out_size) {
    const float* states   = (const float*)d_in[0];
    const int*   actions  = (const int*)d_in[1];
    const int*   tsteps   = (const int*)d_in[2];
    const float* W_se     = (const float*)d_in[3];
    const float* b_se     = (const float*)d_in[4];
    const float* act_tab  = (const float*)d_in[5];
    const float* pos_emb  = (const float*)d_in[6];
    const float* gpe      = (const float*)d_in[7];
    const float* ln1_g    = (const float*)d_in[8];
    const float* ln1_b    = (const float*)d_in[9];
    const float* Wq       = (const float*)d_in[10];
    const float* bq       = (const float*)d_in[11];
    const float* Wk       = (const float*)d_in[12];
    const float* bk       = (const float*)d_in[13];
    const float* Wv       = (const float*)d_in[14];
    const float* bv       = (const float*)d_in[15];
    const float* Wo       = (const float*)d_in[16];
    const float* bo       = (const float*)d_in[17];
    const float* ln2_g    = (const float*)d_in[18];
    const float* ln2_b    = (const float*)d_in[19];
    const float* W1       = (const float*)d_in[20];
    const float* b1       = (const float*)d_in[21];
    const float* W2       = (const float*)d_in[22];
    const float* b2       = (const float*)d_in[23];
    const float* lnf_g    = (const float*)d_in[24];
    const float* lnf_b    = (const float*)d_in[25];
    const float* W_head   = (const float*)d_in[26];
    float* out = (float*)d_out;

    float* F = nullptr;
    cudaGetSymbolAddress((void**)&F, g_f32);
    float* BQKV = nullptr;
    cudaGetSymbolAddress((void**)&BQKV, g_bqkv);
    __half* HP = nullptr;
    cudaGetSymbolAddress((void**)&HP, g_hp);

    float* X  = F;
    float* X2 = X  + N_BLC;
    float* HF = X2 + N_BLC;

    size_t off = 0;
    auto take = [&](size_t n) { __half* p = HP + off; off += n; return p; };
    __half *stH = take(524288), *stL = take(524288);
    __half *wseH = take(131072);
    __half *wAll = take(67108864);     // per layer: [qkv 3.1M][wo 1.0M][w1 2.1M][w2 2.1M]
    __half *hdH = take(4194304);
    __half *HbH = take(N_BLC),   *HbL = take(N_BLC);
    __half *AOH = take(N_BLC),   *AOL = take(N_BLC);
    __half *MIDH = take(2*N_BLC), *MIDL = take(2*N_BLC);
    __half *HFH = take(N_HF),    *HFL = take(N_HF);
    __half *QKVH = take(3*N_BLC), *QKVL = take(3*N_BLC);

    const size_t LW = 8388608;          // per-layer weight stride (halves)
    const size_t OFF_QKV = 0, OFF_WO = 3145728, OFF_W1 = 4194304, OFF_W2 = 6291456;

    const int GSM = 3*ST_HALVES*2;      // 122880 B (3 stages x 40KB)
    const int ATSM = 4*4608*2;          // 36864 B
    cudaFuncSetAttribute(gemm_hk<1,true,false,0>, cudaFuncAttributeMaxDynamicSharedMemorySize, GSM);
    cudaFuncSetAttribute(gemm_hk<0,true,false,2>, cudaFuncAttributeMaxDynamicSharedMemorySize, GSM);
    cudaFuncSetAttribute(gemm_hk<0,true,true,0>,  cudaFuncAttributeMaxDynamicSharedMemorySize, GSM);
    cudaFuncSetAttribute(gemm_hk<2,true,false,2>, cudaFuncAttributeMaxDynamicSharedMemorySize, GSM);
    cudaFuncSetAttribute(gemm_hk<0,false,false,0>,cudaFuncAttributeMaxDynamicSharedMemorySize, GSM);
    cudaFuncSetAttribute(attn_kernel, cudaFuncAttributeMaxDynamicSharedMemorySize, ATSM);

    const int Mx = Bb * Lseq;   // 8192
    const int Mh = Bb * Tt;     // 4096
    dim3 thr(256);

    // ---- prep (batched) ----
    esplit_kernel<<<512, thr>>>(states, stH, stL, Mh * Ss);
    bcat_kernel<<<96, thr>>>(bq, bk, bv, BQKV);
    wsplit_kernel<<<dim3(Cc/32, Ss/32, 1), thr>>>(W_se, wseH, Ss, Cc, 0, 0);
    wsplit_kernel<<<dim3(Cc/32, Cc/32, NLAYER), thr>>>(Wq, wAll + OFF_QKV,            Cc, Cc,   (size_t)Cc*Cc,   LW);
    wsplit_kernel<<<dim3(Cc/32, Cc/32, NLAYER), thr>>>(Wk, wAll + OFF_QKV + 1024*Cc,  Cc, Cc,   (size_t)Cc*Cc,   LW);
    wsplit_kernel<<<dim3(Cc/32, Cc/32, NLAYER), thr>>>(Wv, wAll + OFF_QKV + 2048*Cc,  Cc, Cc,   (size_t)Cc*Cc,   LW);
    wsplit_kernel<<<dim3(Cc/32, Cc/32, NLAYER), thr>>>(Wo, wAll + OFF_WO,             Cc, Cc,   (size_t)Cc*Cc,   LW);
    wsplit_kernel<<<dim3(2*Cc/32, Cc/32, NLAYER), thr>>>(W1, wAll + OFF_W1,           Cc, 2*Cc, (size_t)2*Cc*Cc, LW);
    wsplit_kernel<<<dim3(Cc/32, 2*Cc/32, NLAYER), thr>>>(W2, wAll + OFF_W2,           2*Cc, Cc, (size_t)2*Cc*Cc, LW);
    wsplit_kernel<<<dim3(VOC/32, Cc/32, 1), thr>>>(W_head, hdH, Cc, VOC, 0, 0);

    // ---- state encoder + token assembly ----
    gemm_hk<1,true,false,0><<<dim3(Cc/256, Mh/128), thr, GSM>>>(
        stH, stL, wseH, b_se, nullptr, HF, nullptr, nullptr, Mh, Cc, Ss);
    assemble_kernel<<<Mh, thr>>>(HF, actions, tsteps, act_tab, pos_emb, gpe, X);

    for (int lyr = 0; lyr < NLAYER; lyr++) {
        __half* wqkv = wAll + lyr*LW + OFF_QKV;
        __half* wo   = wAll + lyr*LW + OFF_WO;
        __half* w1   = wAll + lyr*LW + OFF_W1;
        __half* w2   = wAll + lyr*LW + OFF_W2;

        ln_kernel<<<Mx, thr>>>(X, ln1_g + lyr*Cc, ln1_b + lyr*Cc, HbH, HbL, 0);
        gemm_hk<0,true,false,2><<<dim3(3072/256, Mx/128), thr, GSM>>>(
            HbH, HbL, wqkv, BQKV + lyr*3072, nullptr, nullptr, QKVH, QKVL, Mx, 3072, Cc);
        attn_kernel<<<dim3(Lseq/64, Bb*16), dim3(128), ATSM>>>(QKVH, QKVL, AOH, AOL);
        gemm_hk<0,true,true,0><<<dim3(Cc/256, Mx/128), thr, GSM>>>(
            AOH, AOL, wo, bo + lyr*Cc, X, X2, nullptr, nullptr, Mx, Cc, Cc);
        ln_kernel<<<Mx, thr>>>(X2, ln2_g + lyr*Cc, ln2_b + lyr*Cc, HbH, HbL, 0);
        gemm_hk<2,true,false,2><<<dim3(2*Cc/256, Mx/128), thr, GSM>>>(
            HbH, HbL, w1, b1 + lyr*2*Cc, nullptr, nullptr, MIDH, MIDL, Mx, 2*Cc, Cc);
        gemm_hk<0,true,true,0><<<dim3(Cc/256, Mx/128), thr, GSM>>>(
            MIDH, MIDL, w2, b2 + lyr*Cc, X2, X, nullptr, nullptr, Mx, Cc, 2*Cc);
    }

    ln_kernel<<<Mh, thr>>>(X, lnf_g, lnf_b, HFH, HFL, 1);
    gemm_hk<0,false,false,0><<<dim3(VOC/256, Mh/128), thr, GSM>>>(
        HFH, HFL, hdH, nullptr, nullptr, out, nullptr, nullptr, Mh, VOC, Cc);
}

// round 9
// speedup vs baseline: 1.3748x; 1.3748x over previous
#include <cuda_runtime.h>
#include <cuda_fp16.h>
#include <cstdint>

#define Bb 4
#define Tt 1024
#define Ss 128
#define Cc 1024
#define NLAYER 8
#define VOC 4096
#define Lseq 2048

#define N_BLC (Bb*Lseq*Cc)
#define N_HF  (Bb*Tt*Cc)

__device__ float g_f32[2*N_BLC + N_HF];       // X, X2, HF
__device__ float g_bqkv[NLAYER*3072];         // fused qkv bias
__device__ __half g_hp[198311936];            // all fp16 planes (~397MB)

// ---------------- helpers ----------------
__device__ __forceinline__ void ldsm4(uint32_t r[4], const __half* p) {
    uint32_t a = (uint32_t)__cvta_generic_to_shared(p);
    asm volatile("ldmatrix.sync.aligned.m8n8.x4.shared.b16 {%0,%1,%2,%3}, [%4];"
        : "=r"(r[0]), "=r"(r[1]), "=r"(r[2]), "=r"(r[3]) : "r"(a));
}
__device__ __forceinline__ void ldsm4t(uint32_t r[4], const __half* p) {
    uint32_t a = (uint32_t)__cvta_generic_to_shared(p);
    asm volatile("ldmatrix.sync.aligned.m8n8.x4.trans.shared.b16 {%0,%1,%2,%3}, [%4];"
        : "=r"(r[0]), "=r"(r[1]), "=r"(r[2]), "=r"(r[3]) : "r"(a));
}
__device__ __forceinline__ void mma_f16(float c[4], const uint32_t a[4], const uint32_t b[2]) {
    asm volatile("mma.sync.aligned.m16n8k16.row.col.f32.f16.f16.f32 "
        "{%0,%1,%2,%3}, {%4,%5,%6,%7}, {%8,%9}, {%0,%1,%2,%3};"
        : "+f"(c[0]), "+f"(c[1]), "+f"(c[2]), "+f"(c[3])
        : "r"(a[0]), "r"(a[1]), "r"(a[2]), "r"(a[3]), "r"(b[0]), "r"(b[1]));
}
__device__ __forceinline__ void cpa16(__half* dst, const __half* src) {
    uint32_t d = (uint32_t)__cvta_generic_to_shared(dst);
    asm volatile("cp.async.cg.shared.global [%0], [%1], 16;" :: "r"(d), "l"(src));
}
__device__ __forceinline__ void split1h(float v, __half& h, __half& l) {
    h = __float2half_rn(v);
    l = __float2half_rn(v - __half2float(h));
}
__device__ __forceinline__ float fast_exp(float x) {
    x = fmaxf(x, -80.f);
    float y = x * 1.44269504088896f;
    float t = y + 12582912.f;
    int ni = __float_as_int(t) - 0x4B400000;
    float f = y - (t - 12582912.f);
    float p = 1.33335581e-3f;
    p = fmaf(p, f, 9.61812910e-3f);
    p = fmaf(p, f, 5.55041087e-2f);
    p = fmaf(p, f, 2.40226507e-1f);
    p = fmaf(p, f, 6.93147180e-1f);
    p = fmaf(p, f, 1.0f);
    return p * __int_as_float((ni + 127) << 23);
}

// ---------------- GEMM: out = act((Ah[+Al])@W16^T + bias)(+res) ----------------
// R6 geometry: CTA 128x128, BK=32, 8 warps (4x2) of 32x64, 3-stage cp.async.
// TERMS=2: A hi+lo planes (exact A). TERMS=1: A single fp16 plane.
// PL: 0=fp32 out, 1=1 plane, 2=2 planes.
template<int ACT, bool HASBIAS, bool HASRES, int PL, int TERMS>
__global__ __launch_bounds__(256, 2) void gemm_hk(
    const __half* __restrict__ Ah, const __half* __restrict__ Al,
    const __half* __restrict__ Wh,
    const float* __restrict__ bias, const float* __restrict__ res,
    float* __restrict__ out, __half* __restrict__ outH, __half* __restrict__ outL,
    int M, int N, int K)
{
    extern __shared__ __half sm[];
    const int TILE = 128*40;
    const int STH = (1 + TERMS) * TILE;      // halves per stage
    int tid = threadIdx.x, lane = tid & 31, warp = tid >> 5;
    int bm = blockIdx.y * 128, bn = blockIdx.x * 128;
    int wm = (warp >> 1) * 32, wn = (warp & 1) * 64;

    float acc[2][8][4];
    #pragma unroll
    for (int i = 0; i < 2; i++)
        #pragma unroll
        for (int j = 0; j < 8; j++)
            #pragma unroll
            for (int q = 0; q < 4; q++) acc[i][j][q] = 0.f;

    int niter = K >> 5;

    // (1+TERMS)*512 16B-chunks per stage; tile0=Ah, [tile1=Al], last=W
    #define ISSUE(ST, K0) do {                                                  \
        int _k0 = (K0);                                                         \
        _Pragma("unroll")                                                       \
        for (int _i = 0; _i < 2*(1+TERMS); _i++) {                              \
            int _id = tid + (_i << 8);                                          \
            int _tile = _id >> 9;                                               \
            int _r = (_id >> 2) & 127;                                          \
            int _c = (_id & 3) << 3;                                            \
            const __half* _src =                                                \
                (_tile == 0) ? Ah + (size_t)(bm + _r) * K + _k0 + _c :          \
                (TERMS == 2 && _tile == 1) ? Al + (size_t)(bm + _r) * K + _k0 + _c : \
                               Wh + (size_t)(bn + _r) * K + _k0 + _c;           \
            cpa16(sm + (ST)*STH + _tile*TILE + _r*40 + _c, _src);               \
        }                                                                       \
        asm volatile("cp.async.commit_group;" ::: "memory");                    \
    } while (0)

    ISSUE(0, 0);
    if (niter > 1) ISSUE(1, 32);
    for (int it = 0; it < niter; ++it) {
        if (it + 1 < niter) {
            asm volatile("cp.async.wait_group 1;" ::: "memory");
        } else {
            asm volatile("cp.async.wait_group 0;" ::: "memory");
        }
        __syncthreads();
        if (it + 2 < niter) ISSUE((it + 2) % 3, (it + 2) << 5);

        int st = it % 3;
        const __half* AshH = sm + st*STH;
        const __half* AshL = AshH + TILE;            // valid only if TERMS==2
        const __half* BshW = AshH + TERMS*TILE;

        #pragma unroll
        for (int ks = 0; ks < 2; ks++) {
            uint32_t aH[2][4], aL[2][4];
            #pragma unroll
            for (int mi = 0; mi < 2; mi++) {
                int row = wm + mi*16 + (lane & 15);
                int col = ks*16 + ((lane >> 4) << 3);
                ldsm4(aH[mi], &AshH[row*40 + col]);
                if (TERMS == 2) ldsm4(aL[mi], &AshL[row*40 + col]);
            }
            uint32_t bW[8][2];
            #pragma unroll
            for (int pi = 0; pi < 4; pi++) {
                int nr = wn + pi*16 + ((lane >> 4) << 3) + (lane & 7);
                int kc = ks*16 + (((lane >> 3) & 1) << 3);
                uint32_t t[4];
                ldsm4(t, &BshW[nr*40 + kc]);
                bW[2*pi][0] = t[0]; bW[2*pi][1] = t[1];
                bW[2*pi+1][0] = t[2]; bW[2*pi+1][1] = t[3];
            }
            #pragma unroll
            for (int mi = 0; mi < 2; mi++)
                #pragma unroll
                for (int nj = 0; nj < 8; nj++) {
                    mma_f16(acc[mi][nj], aH[mi], bW[nj]);
                    if (TERMS == 2) mma_f16(acc[mi][nj], aL[mi], bW[nj]);
                }
        }
    }
    #undef ISSUE

    int g = lane >> 2, tg = lane & 3;
    #pragma unroll
    for (int mi = 0; mi < 2; mi++)
        #pragma unroll
        for (int nj = 0; nj < 8; nj++) {
            int r0 = bm + wm + mi*16 + g;
            int c0 = bn + wn + nj*8 + tg*2;
            float v[4];
            #pragma unroll
            for (int q = 0; q < 4; q++) {
                float x = acc[mi][nj][q];
                if (HASBIAS) x += bias[c0 + (q & 1)];
                if (ACT == 1) x = tanhf(x);
                else if (ACT == 2) x = 0.5f * x * (1.0f + erff(x * 0.70710678f));
                v[q] = x;
            }
            if (PL == 2) {
                #pragma unroll
                for (int h2 = 0; h2 < 2; h2++) {
                    int r = r0 + h2*8;
                    __half h0, h1, l0, l1;
                    split1h(v[2*h2], h0, l0);
                    split1h(v[2*h2+1], h1, l1);
                    __half2 hh; hh.x = h0; hh.y = h1;
                    __half2 ll; ll.x = l0; ll.y = l1;
                    *(__half2*)&outH[(size_t)r*N + c0] = hh;
                    *(__half2*)&outL[(size_t)r*N + c0] = ll;
                }
            } else if (PL == 1) {
                #pragma unroll
                for (int h2 = 0; h2 < 2; h2++) {
                    int r = r0 + h2*8;
                    __half2 hh;
                    hh.x = __float2half_rn(v[2*h2]);
                    hh.y = __float2half_rn(v[2*h2+1]);
                    *(__half2*)&outH[(size_t)r*N + c0] = hh;
                }
            } else {
                #pragma unroll
                for (int q = 0; q < 4; q++) {
                    int r = r0 + (q >> 1) * 8, c = c0 + (q & 1);
                    float x = v[q];
                    if (HASRES) x += res[(size_t)r * N + c];
                    out[(size_t)r * N + c] = x;
                }
            }
        }
}

// ---------------- LayerNorm -> fp16 planes (lo optional) ----------------
__global__ __launch_bounds__(256) void ln_kernel(
    const float* __restrict__ x, const float* __restrict__ g,
    const float* __restrict__ b, __half* __restrict__ oh,
    __half* __restrict__ ol, int gather)
{
    int row = blockIdx.x;
    int src = gather ? ((row / Tt) * Lseq + 2 * (row % Tt) + 1) : row;
    float4 v = ((const float4*)(x + (size_t)src * Cc))[threadIdx.x];
    float s = v.x + v.y + v.z + v.w;
    float q = v.x*v.x + v.y*v.y + v.z*v.z + v.w*v.w;
    #pragma unroll
    for (int o = 16; o; o >>= 1) {
        s += __shfl_xor_sync(0xffffffffu, s, o);
        q += __shfl_xor_sync(0xffffffffu, q, o);
    }
    __shared__ float ss[8], sq[8];
    int w = threadIdx.x >> 5;
    if ((threadIdx.x & 31) == 0) { ss[w] = s; sq[w] = q; }
    __syncthreads();
    s = 0.f; q = 0.f;
    #pragma unroll
    for (int i = 0; i < 8; i++) { s += ss[i]; q += sq[i]; }
    float mean = s * (1.0f / Cc);
    float rstd = rsqrtf(q * (1.0f / Cc) - mean * mean + 1e-5f);
    float4 gv = ((const float4*)g)[threadIdx.x];
    float4 bv = ((const float4*)b)[threadIdx.x];
    float o4[4];
    o4[0] = (v.x - mean) * rstd * gv.x + bv.x;
    o4[1] = (v.y - mean) * rstd * gv.y + bv.y;
    o4[2] = (v.z - mean) * rstd * gv.z + bv.z;
    o4[3] = (v.w - mean) * rstd * gv.w + bv.w;
    size_t base = (size_t)row * Cc + threadIdx.x * 4;
    __half h[4], l[4];
    #pragma unroll
    for (int e = 0; e < 4; e++) split1h(o4[e], h[e], l[e]);
    __half2 p;
    p.x=h[0]; p.y=h[1]; *(__half2*)&oh[base]   = p;
    p.x=h[2]; p.y=h[3]; *(__half2*)&oh[base+2] = p;
    if (ol) {
        p.x=l[0]; p.y=l[1]; *(__half2*)&ol[base]   = p;
        p.x=l[2]; p.y=l[3]; *(__half2*)&ol[base+2] = p;
    }
}

// ---------------- token assembly ----------------
__global__ __launch_bounds__(256) void assemble_kernel(
    const float* __restrict__ SE, const int* __restrict__ actions,
    const int* __restrict__ tsteps, const float* __restrict__ act_table,
    const float* __restrict__ pos_emb, const float* __restrict__ gpe_table,
    float* __restrict__ x)
{
    int bt = blockIdx.x;
    int b = bt / Tt, t = bt % Tt;
    int a = actions[bt];
    int ts = tsteps[bt];
    size_t row0 = (size_t)(b * Lseq + 2*t) * Cc;
    for (int c = threadIdx.x; c < Cc; c += 256) {
        float gp = gpe_table[(size_t)ts * Cc + c];
        x[row0 + c]      = SE[(size_t)bt * Cc + c] + gp + pos_emb[(size_t)(2*t) * Cc + c];
        x[row0 + Cc + c] = tanhf(act_table[(size_t)a * Cc + c]) + gp + pos_emb[(size_t)(2*t+1) * Cc + c];
    }
}

// ---------------- MMA flash attention (fp16 2-term Q/P), fused QKV input ----------------
// Output: hi plane only (WO GEMM is 1-term).
__global__ __launch_bounds__(128) void attn_kernel(
    const __half* __restrict__ QKVH, const __half* __restrict__ QKVL,
    __half* __restrict__ OutH)
{
    extern __shared__ __half smb[];
    __half* sQH = smb;
    __half* sQL = smb + 4608;
    __half* sKH = smb + 2*4608;
    __half* sVH = smb + 3*4608;

    int tid = threadIdx.x, lane = tid & 31, wid = tid >> 5;
    int b = blockIdx.y >> 4, h = blockIdx.y & 15;
    int q0 = blockIdx.x * 64;
    size_t gbase = (size_t)b * Lseq * 3072 + h * 64;

    #pragma unroll
    for (int i = 0; i < 8; i++) {
        int id = tid + i*128;
        int pl = id >> 9;
        int r = (id >> 3) & 63;
        int c = (id & 7) << 3;
        cpa16((pl ? sQL : sQH) + r*72 + c,
              (pl ? QKVL : QKVH) + gbase + (size_t)(q0 + r)*3072 + c);
    }
    asm volatile("cp.async.commit_group;" ::: "memory");

    float m0 = -1e30f, m1 = -1e30f, lsum0 = 0.f, lsum1 = 0.f;
    float O[8][4];
    #pragma unroll
    for (int f = 0; f < 8; f++)
        #pragma unroll
        for (int q = 0; q < 4; q++) O[f][q] = 0.f;

    int g = lane >> 2, tg = lane & 3;
    int wq = wid * 16;
    int row0 = q0 + wq + g, row1 = row0 + 8;
    int ntiles = blockIdx.x + 1;

    for (int kt = 0; kt < ntiles; kt++) {
        int j0 = kt * 64;
        #pragma unroll
        for (int i = 0; i < 8; i++) {
            int id = tid + i*128;
            int pl = id >> 9;                 // 0: K, 1: V
            int r = (id >> 3) & 63;
            int c = (id & 7) << 3;
            const __half* src = QKVH + gbase + (size_t)(j0 + r)*3072 + (pl ? 2048 : 1024) + c;
            __half* dst = (pl ? sVH : sKH) + r*72 + c;
            cpa16(dst, src);
        }
        asm volatile("cp.async.commit_group;" ::: "memory");
        asm volatile("cp.async.wait_group 0;" ::: "memory");
        __syncthreads();

        float S[8][4];
        #pragma unroll
        for (int f = 0; f < 8; f++)
            #pragma unroll
            for (int q = 0; q < 4; q++) S[f][q] = 0.f;

        #pragma unroll
        for (int ks = 0; ks < 4; ks++) {
            int arow = wq + (lane & 15);
            int acol = ks*16 + ((lane >> 4) << 3);
            uint32_t aH[4], aL[4];
            ldsm4(aH, sQH + arow*72 + acol);
            ldsm4(aL, sQL + arow*72 + acol);
            #pragma unroll
            for (int nb = 0; nb < 4; nb++) {
                int nr = nb*16 + ((lane >> 4) << 3) + (lane & 7);
                int kc = ks*16 + (((lane >> 3) & 1) << 3);
                uint32_t tK[4];
                ldsm4(tK, sKH + nr*72 + kc);
                uint32_t b0[2] = {tK[0], tK[1]}, b1[2] = {tK[2], tK[3]};
                mma_f16(S[2*nb],   aH, b0);
                mma_f16(S[2*nb],   aL, b0);
                mma_f16(S[2*nb+1], aH, b1);
                mma_f16(S[2*nb+1], aL, b1);
            }
        }

        #pragma unroll
        for (int f = 0; f < 8; f++) {
            int kcol = j0 + f*8 + tg*2;
            float v0 = S[f][0]*0.125f; if (kcol   > row0) v0 = -1e30f;
            float v1 = S[f][1]*0.125f; if (kcol+1 > row0) v1 = -1e30f;
            float v2 = S[f][2]*0.125f; if (kcol   > row1) v2 = -1e30f;
            float v3 = S[f][3]*0.125f; if (kcol+1 > row1) v3 = -1e30f;
            S[f][0] = v0; S[f][1] = v1; S[f][2] = v2; S[f][3] = v3;
        }
        float r0m = -1e30f, r1m = -1e30f;
        #pragma unroll
        for (int f = 0; f < 8; f++) {
            r0m = fmaxf(r0m, fmaxf(S[f][0], S[f][1]));
            r1m = fmaxf(r1m, fmaxf(S[f][2], S[f][3]));
        }
        r0m = fmaxf(r0m, __shfl_xor_sync(0xffffffffu, r0m, 1));
        r0m = fmaxf(r0m, __shfl_xor_sync(0xffffffffu, r0m, 2));
        r1m = fmaxf(r1m, __shfl_xor_sync(0xffffffffu, r1m, 1));
        r1m = fmaxf(r1m, __shfl_xor_sync(0xffffffffu, r1m, 2));
        float mn0 = fmaxf(m0, r0m), mn1 = fmaxf(m1, r1m);
        float a0 = fast_exp(m0 - mn0), a1 = fast_exp(m1 - mn1);
        m0 = mn0; m1 = mn1;

        float s0 = 0.f, s1 = 0.f;
        #pragma unroll
        for (int f = 0; f < 8; f++) {
            float p0 = fast_exp(S[f][0] - mn0);
            float p1 = fast_exp(S[f][1] - mn0);
            float p2 = fast_exp(S[f][2] - mn1);
            float p3 = fast_exp(S[f][3] - mn1);
            S[f][0] = p0; S[f][1] = p1; S[f][2] = p2; S[f][3] = p3;
            s0 += p0 + p1; s1 += p2 + p3;
        }
        s0 += __shfl_xor_sync(0xffffffffu, s0, 1);
        s0 += __shfl_xor_sync(0xffffffffu, s0, 2);
        s1 += __shfl_xor_sync(0xffffffffu, s1, 1);
        s1 += __shfl_xor_sync(0xffffffffu, s1, 2);
        lsum0 = lsum0 * a0 + s0;
        lsum1 = lsum1 * a1 + s1;
        #pragma unroll
        for (int f = 0; f < 8; f++) {
            O[f][0] *= a0; O[f][1] *= a0;
            O[f][2] *= a1; O[f][3] *= a1;
        }

        #pragma unroll
        for (int ks2 = 0; ks2 < 4; ks2++) {
            uint32_t pH[4], pL[4];
            #pragma unroll
            for (int hf = 0; hf < 2; hf++) {
                int f = 2*ks2 + hf;
                __half h0,h1,h2,h3,l0,l1,l2,l3;
                split1h(S[f][0], h0, l0); split1h(S[f][1], h1, l1);
                split1h(S[f][2], h2, l2); split1h(S[f][3], h3, l3);
                __half2 t;
                t.x=h0; t.y=h1; pH[hf*2+0] = *(uint32_t*)&t;
                t.x=h2; t.y=h3; pH[hf*2+1] = *(uint32_t*)&t;
                t.x=l0; t.y=l1; pL[hf*2+0] = *(uint32_t*)&t;
                t.x=l2; t.y=l3; pL[hf*2+1] = *(uint32_t*)&t;
            }
            int vrow = ks2*16 + (lane & 15);
            #pragma unroll
            for (int nb = 0; nb < 4; nb++) {
                int vcol = nb*16 + ((lane >> 4) << 3);
                uint32_t tV[4];
                ldsm4t(tV, sVH + vrow*72 + vcol);
                uint32_t b0[2] = {tV[0], tV[1]}, b1[2] = {tV[2], tV[3]};
                mma_f16(O[2*nb],   pH, b0);
                mma_f16(O[2*nb],   pL, b0);
                mma_f16(O[2*nb+1], pH, b1);
                mma_f16(O[2*nb+1], pL, b1);
            }
        }
        __syncthreads();
    }

    float rl0 = 1.f / lsum0, rl1 = 1.f / lsum1;
    size_t t0 = (size_t)(b*Lseq + row0), t1 = (size_t)(b*Lseq + row1);
    #pragma unroll
    for (int f = 0; f < 8; f++) {
        int gcol = h*64 + f*8 + tg*2;
        __half2 ph;
        ph.x = __float2half_rn(O[f][0]*rl0);
        ph.y = __float2half_rn(O[f][1]*rl0);
        *(__half2*)&OutH[t0*Cc + gcol] = ph;
        ph.x = __float2half_rn(O[f][2]*rl1);
        ph.y = __float2half_rn(O[f][3]*rl1);
        *(__half2*)&OutH[t1*Cc + gcol] = ph;
    }
}

// ---------------- batched weight transpose + fp16 ----------------
__global__ __launch_bounds__(256) void wsplit_kernel(
    const float* __restrict__ W, __half* __restrict__ Wh, int K, int N,
    size_t inStride, size_t outStride)
{
    const float* Wz = W + (size_t)blockIdx.z * inStride;
    __half* Whz = Wh + (size_t)blockIdx.z * outStride;
    __shared__ float tile[32][33];
    int k0 = blockIdx.y * 32, n0 = blockIdx.x * 32;
    int tx = threadIdx.x & 31, ty = threadIdx.x >> 5;
    #pragma unroll
    for (int r = ty; r < 32; r += 8)
        tile[r][tx] = Wz[(size_t)(k0 + r) * N + n0 + tx];
    __syncthreads();
    #pragma unroll
    for (int r = ty; r < 32; r += 8)
        Whz[(size_t)(n0 + r) * K + k0 + tx] = __float2half_rn(tile[tx][r]);
}

// ---------------- fused QKV bias concat ----------------
__global__ __launch_bounds__(256) void bcat_kernel(
    const float* __restrict__ bq, const float* __restrict__ bk,
    const float* __restrict__ bv, float* __restrict__ outb)
{
    int i = blockIdx.x * 256 + threadIdx.x;
    if (i < NLAYER * 3072) {
        int lyr = i / 3072, c = i % 3072;
        float v = (c < 1024) ? bq[lyr*1024 + c]
                : (c < 2048) ? bk[lyr*1024 + c - 1024]
                             : bv[lyr*1024 + c - 2048];
        outb[i] = v;
    }
}

// ---------------- elementwise 2-plane split (states) ----------------
__global__ __launch_bounds__(256) void esplit_kernel(
    const float* __restrict__ x, __half* __restrict__ h,
    __half* __restrict__ l, int n)
{
    int i = (blockIdx.x * 256 + threadIdx.x) * 4;
    if (i < n) {
        float4 v = *(const float4*)&x[i];
        float a[4] = {v.x, v.y, v.z, v.w};
        __half hh[4], ll[4];
        #pragma unroll
        for (int e = 0; e < 4; e++) split1h(a[e], hh[e], ll[e]);
        __half2 p;
        p.x=hh[0]; p.y=hh[1]; *(__half2*)&h[i]   = p;
        p.x=hh[2]; p.y=hh[3]; *(__half2*)&h[i+2] = p;
        p.x=ll[0]; p.y=ll[1]; *(__half2*)&l[i]   = p;
        p.x=ll[2]; p.y=ll[3]; *(__half2*)&l[i+2] = p;
    }
}

// ---------------- launcher ----------------
extern "C" void kernel_launch(void* const* d_in, const int* in_sizes, int n_in,
                              void* d_out, int out_size) {
    const float* states   = (const float*)d_in[0];
    const int*   actions  = (const int*)d_in[1];
    const int*   tsteps   = (const int*)d_in[2];
    const float* W_se     = (const float*)d_in[3];
    const float* b_se     = (const float*)d_in[4];
    const float* act_tab  = (const float*)d_in[5];
    const float* pos_emb  = (const float*)d_in[6];
    const float* gpe      = (const float*)d_in[7];
    const float* ln1_g    = (const float*)d_in[8];
    const float* ln1_b    = (const float*)d_in[9];
    const float* Wq       = (const float*)d_in[10];
    const float* bq       = (const float*)d_in[11];
    const float* Wk       = (const float*)d_in[12];
    const float* bk       = (const float*)d_in[13];
    const float* Wv       = (const float*)d_in[14];
    const float* bv       = (const float*)d_in[15];
    const float* Wo       = (const float*)d_in[16];
    const float* bo       = (const float*)d_in[17];
    const float* ln2_g    = (const float*)d_in[18];
    const float* ln2_b    = (const float*)d_in[19];
    const float* W1       = (const float*)d_in[20];
    const float* b1       = (const float*)d_in[21];
    const float* W2       = (const float*)d_in[22];
    const float* b2       = (const float*)d_in[23];
    const float* lnf_g    = (const float*)d_in[24];
    const float* lnf_b    = (const float*)d_in[25];
    const float* W_head   = (const float*)d_in[26];
    float* out = (float*)d_out;

    float* F = nullptr;
    cudaGetSymbolAddress((void**)&F, g_f32);
    float* BQKV = nullptr;
    cudaGetSymbolAddress((void**)&BQKV, g_bqkv);
    __half* HP = nullptr;
    cudaGetSymbolAddress((void**)&HP, g_hp);

    float* X  = F;
    float* X2 = X  + N_BLC;
    float* HF = X2 + N_BLC;

    size_t off = 0;
    auto take = [&](size_t n) { __half* p = HP + off; off += n; return p; };
    __half *stH = take(524288), *stL = take(524288);
    __half *wseH = take(131072);
    __half *wAll = take(67108864);     // per layer: [qkv 3.1M][wo 1.0M][w1 2.1M][w2 2.1M]
    __half *hdH = take(4194304);
    __half *HbH = take(N_BLC),   *HbL = take(N_BLC);
    __half *AOH = take(N_BLC);
    __half *MIDH = take(2*N_BLC);
    __half *HFH = take(N_HF);
    __half *QKVH = take(3*N_BLC), *QKVL = take(3*N_BLC);

    const size_t LW = 8388608;          // per-layer weight stride (halves)
    const size_t OFF_QKV = 0, OFF_WO = 3145728, OFF_W1 = 4194304, OFF_W2 = 6291456;

    const int GSM2 = 3*3*5120*2;        // 92160 B (3 stages, 3 tiles)
    const int GSM1 = 3*2*5120*2;        // 61440 B (3 stages, 2 tiles)
    const int ATSM = 4*4608*2;          // 36864 B
    cudaFuncSetAttribute(gemm_hk<1,true,false,0,2>, cudaFuncAttributeMaxDynamicSharedMemorySize, GSM2);
    cudaFuncSetAttribute(gemm_hk<0,true,false,2,2>, cudaFuncAttributeMaxDynamicSharedMemorySize, GSM2);
    cudaFuncSetAttribute(gemm_hk<0,true,true,0,1>,  cudaFuncAttributeMaxDynamicSharedMemorySize, GSM1);
    cudaFuncSetAttribute(gemm_hk<2,true,false,1,1>, cudaFuncAttributeMaxDynamicSharedMemorySize, GSM1);
    cudaFuncSetAttribute(gemm_hk<0,false,false,0,1>,cudaFuncAttributeMaxDynamicSharedMemorySize, GSM1);
    cudaFuncSetAttribute(attn_kernel, cudaFuncAttributeMaxDynamicSharedMemorySize, ATSM);

    const int Mx = Bb * Lseq;   // 8192
    const int Mh = Bb * Tt;     // 4096
    dim3 thr(256);

    // ---- prep (batched) ----
    esplit_kernel<<<512, thr>>>(states, stH, stL, Mh * Ss);
    bcat_kernel<<<96, thr>>>(bq, bk, bv, BQKV);
    wsplit_kernel<<<dim3(Cc/32, Ss/32, 1), thr>>>(W_se, wseH, Ss, Cc, 0, 0);
    wsplit_kernel<<<dim3(Cc/32, Cc/32, NLAYER), thr>>>(Wq, wAll + OFF_QKV,            Cc, Cc,   (size_t)Cc*Cc,   LW);
    wsplit_kernel<<<dim3(Cc/32, Cc/32, NLAYER), thr>>>(Wk, wAll + OFF_QKV + 1024*Cc,  Cc, Cc,   (size_t)Cc*Cc,   LW);
    wsplit_kernel<<<dim3(Cc/32, Cc/32, NLAYER), thr>>>(Wv, wAll + OFF_QKV + 2048*Cc,  Cc, Cc,   (size_t)Cc*Cc,   LW);
    wsplit_kernel<<<dim3(Cc/32, Cc/32, NLAYER), thr>>>(Wo, wAll + OFF_WO,             Cc, Cc,   (size_t)Cc*Cc,   LW);
    wsplit_kernel<<<dim3(2*Cc/32, Cc/32, NLAYER), thr>>>(W1, wAll + OFF_W1,           Cc, 2*Cc, (size_t)2*Cc*Cc, LW);
    wsplit_kernel<<<dim3(Cc/32, 2*Cc/32, NLAYER), thr>>>(W2, wAll + OFF_W2,           2*Cc, Cc, (size_t)2*Cc*Cc, LW);
    wsplit_kernel<<<dim3(VOC/32, Cc/32, 1), thr>>>(W_head, hdH, Cc, VOC, 0, 0);

    // ---- state encoder + token assembly ----
    gemm_hk<1,true,false,0,2><<<dim3(Cc/128, Mh/128), thr, GSM2>>>(
        stH, stL, wseH, b_se, nullptr, HF, nullptr, nullptr, Mh, Cc, Ss);
    assemble_kernel<<<Mh, thr>>>(HF, actions, tsteps, act_tab, pos_emb, gpe, X);

    for (int lyr = 0; lyr < NLAYER; lyr++) {
        __half* wqkv = wAll + lyr*LW + OFF_QKV;
        __half* wo   = wAll + lyr*LW + OFF_WO;
        __half* w1   = wAll + lyr*LW + OFF_W1;
        __half* w2   = wAll + lyr*LW + OFF_W2;

        ln_kernel<<<Mx, thr>>>(X, ln1_g + lyr*Cc, ln1_b + lyr*Cc, HbH, HbL, 0);
        gemm_hk<0,true,false,2,2><<<dim3(3072/128, Mx/128), thr, GSM2>>>(
            HbH, HbL, wqkv, BQKV + lyr*3072, nullptr, nullptr, QKVH, QKVL, Mx, 3072, Cc);
        attn_kernel<<<dim3(Lseq/64, Bb*16), dim3(128), ATSM>>>(QKVH, QKVL, AOH);
        gemm_hk<0,true,true,0,1><<<dim3(Cc/128, Mx/128), thr, GSM1>>>(
            AOH, nullptr, wo, bo + lyr*Cc, X, X2, nullptr, nullptr, Mx, Cc, Cc);
        ln_kernel<<<Mx, thr>>>(X2, ln2_g + lyr*Cc, ln2_b + lyr*Cc, HbH, nullptr, 0);
        gemm_hk<2,true,false,1,1><<<dim3(2*Cc/128, Mx/128), thr, GSM1>>>(
            HbH, nullptr, w1, b1 + lyr*2*Cc, nullptr, nullptr, MIDH, nullptr, Mx, 2*Cc, Cc);
        gemm_hk<0,true,true,0,1><<<dim3(Cc/128, Mx/128), thr, GSM1>>>(
            MIDH, nullptr, w2, b2 + lyr*Cc, X2, X, nullptr, nullptr, Mx, Cc, 2*Cc);
    }

    ln_kernel<<<Mh, thr>>>(X, lnf_g, lnf_b, HFH, nullptr, 1);
    gemm_hk<0,false,false,0,1><<<dim3(VOC/128, Mh/128), thr, GSM1>>>(
        HFH, nullptr, hdH, nullptr, nullptr, out, nullptr, nullptr, Mh, VOC, Cc);
}

// round 10
// speedup vs baseline: 1.5745x; 1.1453x over previous
#include <cuda_runtime.h>
#include <cuda_fp16.h>
#include <cstdint>

#define Bb 4
#define Tt 1024
#define Ss 128
#define Cc 1024
#define NLAYER 8
#define VOC 4096
#define Lseq 2048

#define N_BLC (Bb*Lseq*Cc)
#define N_HF  (Bb*Tt*Cc)

__device__ float g_f32[2*N_BLC + N_HF];       // X, X2, HF
__device__ float g_bqkv[NLAYER*3072];         // fused qkv bias
__device__ __half g_hp[198311936];            // all fp16 planes (~397MB)

// ---------------- helpers ----------------
__device__ __forceinline__ void ldsm4(uint32_t r[4], const __half* p) {
    uint32_t a = (uint32_t)__cvta_generic_to_shared(p);
    asm volatile("ldmatrix.sync.aligned.m8n8.x4.shared.b16 {%0,%1,%2,%3}, [%4];"
        : "=r"(r[0]), "=r"(r[1]), "=r"(r[2]), "=r"(r[3]) : "r"(a));
}
__device__ __forceinline__ void ldsm4t(uint32_t r[4], const __half* p) {
    uint32_t a = (uint32_t)__cvta_generic_to_shared(p);
    asm volatile("ldmatrix.sync.aligned.m8n8.x4.trans.shared.b16 {%0,%1,%2,%3}, [%4];"
        : "=r"(r[0]), "=r"(r[1]), "=r"(r[2]), "=r"(r[3]) : "r"(a));
}
__device__ __forceinline__ void mma_f16(float c[4], const uint32_t a[4], const uint32_t b[2]) {
    asm volatile("mma.sync.aligned.m16n8k16.row.col.f32.f16.f16.f32 "
        "{%0,%1,%2,%3}, {%4,%5,%6,%7}, {%8,%9}, {%0,%1,%2,%3};"
        : "+f"(c[0]), "+f"(c[1]), "+f"(c[2]), "+f"(c[3])
        : "r"(a[0]), "r"(a[1]), "r"(a[2]), "r"(a[3]), "r"(b[0]), "r"(b[1]));
}
__device__ __forceinline__ void cpa16(__half* dst, const __half* src) {
    uint32_t d = (uint32_t)__cvta_generic_to_shared(dst);
    asm volatile("cp.async.cg.shared.global [%0], [%1], 16;" :: "r"(d), "l"(src));
}
__device__ __forceinline__ void split1h(float v, __half& h, __half& l) {
    h = __float2half_rn(v);
    l = __float2half_rn(v - __half2float(h));
}
__device__ __forceinline__ float fast_exp(float x) {
    x = fmaxf(x, -80.f);
    float y = x * 1.44269504088896f;
    float t = y + 12582912.f;
    int ni = __float_as_int(t) - 0x4B400000;
    float f = y - (t - 12582912.f);
    float p = 1.33335581e-3f;
    p = fmaf(p, f, 9.61812910e-3f);
    p = fmaf(p, f, 5.55041087e-2f);
    p = fmaf(p, f, 2.40226507e-1f);
    p = fmaf(p, f, 6.93147180e-1f);
    p = fmaf(p, f, 1.0f);
    return p * __int_as_float((ni + 127) << 23);
}

// ---------------- GEMM: out = act((Ah[+Al])@W16^T + bias)(+res) ----------------
// R6 geometry: CTA 128x128, BK=32, 8 warps (4x2) of 32x64, 3-stage cp.async.
// TERMS=2: A hi+lo planes (exact A). TERMS=1: A single fp16 plane.
// PL: 0=fp32 out, 1=1 plane, 2=2 planes.
template<int ACT, bool HASBIAS, bool HASRES, int PL, int TERMS>
__global__ __launch_bounds__(256, 2) void gemm_hk(
    const __half* __restrict__ Ah, const __half* __restrict__ Al,
    const __half* __restrict__ Wh,
    const float* __restrict__ bias, const float* __restrict__ res,
    float* __restrict__ out, __half* __restrict__ outH, __half* __restrict__ outL,
    int M, int N, int K)
{
    extern __shared__ __half sm[];
    const int TILE = 128*40;
    const int STH = (1 + TERMS) * TILE;      // halves per stage
    int tid = threadIdx.x, lane = tid & 31, warp = tid >> 5;
    int bm = blockIdx.y * 128, bn = blockIdx.x * 128;
    int wm = (warp >> 1) * 32, wn = (warp & 1) * 64;

    float acc[2][8][4];
    #pragma unroll
    for (int i = 0; i < 2; i++)
        #pragma unroll
        for (int j = 0; j < 8; j++)
            #pragma unroll
            for (int q = 0; q < 4; q++) acc[i][j][q] = 0.f;

    int niter = K >> 5;

    // (1+TERMS)*512 16B-chunks per stage; tile0=Ah, [tile1=Al], last=W
    #define ISSUE(ST, K0) do {                                                  \
        int _k0 = (K0);                                                         \
        _Pragma("unroll")                                                       \
        for (int _i = 0; _i < 2*(1+TERMS); _i++) {                              \
            int _id = tid + (_i << 8);                                          \
            int _tile = _id >> 9;                                               \
            int _r = (_id >> 2) & 127;                                          \
            int _c = (_id & 3) << 3;                                            \
            const __half* _src =                                                \
                (_tile == 0) ? Ah + (size_t)(bm + _r) * K + _k0 + _c :          \
                (TERMS == 2 && _tile == 1) ? Al + (size_t)(bm + _r) * K + _k0 + _c : \
                               Wh + (size_t)(bn + _r) * K + _k0 + _c;           \
            cpa16(sm + (ST)*STH + _tile*TILE + _r*40 + _c, _src);               \
        }                                                                       \
        asm volatile("cp.async.commit_group;" ::: "memory");                    \
    } while (0)

    ISSUE(0, 0);
    if (niter > 1) ISSUE(1, 32);
    for (int it = 0; it < niter; ++it) {
        if (it + 1 < niter) {
            asm volatile("cp.async.wait_group 1;" ::: "memory");
        } else {
            asm volatile("cp.async.wait_group 0;" ::: "memory");
        }
        __syncthreads();
        if (it + 2 < niter) ISSUE((it + 2) % 3, (it + 2) << 5);

        int st = it % 3;
        const __half* AshH = sm + st*STH;
        const __half* AshL = AshH + TILE;            // valid only if TERMS==2
        const __half* BshW = AshH + TERMS*TILE;

        #pragma unroll
        for (int ks = 0; ks < 2; ks++) {
            uint32_t aH[2][4], aL[2][4];
            #pragma unroll
            for (int mi = 0; mi < 2; mi++) {
                int row = wm + mi*16 + (lane & 15);
                int col = ks*16 + ((lane >> 4) << 3);
                ldsm4(aH[mi], &AshH[row*40 + col]);
                if (TERMS == 2) ldsm4(aL[mi], &AshL[row*40 + col]);
            }
            uint32_t bW[8][2];
            #pragma unroll
            for (int pi = 0; pi < 4; pi++) {
                int nr = wn + pi*16 + ((lane >> 4) << 3) + (lane & 7);
                int kc = ks*16 + (((lane >> 3) & 1) << 3);
                uint32_t t[4];
                ldsm4(t, &BshW[nr*40 + kc]);
                bW[2*pi][0] = t[0]; bW[2*pi][1] = t[1];
                bW[2*pi+1][0] = t[2]; bW[2*pi+1][1] = t[3];
            }
            #pragma unroll
            for (int mi = 0; mi < 2; mi++)
                #pragma unroll
                for (int nj = 0; nj < 8; nj++) {
                    mma_f16(acc[mi][nj], aH[mi], bW[nj]);
                    if (TERMS == 2) mma_f16(acc[mi][nj], aL[mi], bW[nj]);
                }
        }
    }
    #undef ISSUE

    int g = lane >> 2, tg = lane & 3;
    #pragma unroll
    for (int mi = 0; mi < 2; mi++)
        #pragma unroll
        for (int nj = 0; nj < 8; nj++) {
            int r0 = bm + wm + mi*16 + g;
            int c0 = bn + wn + nj*8 + tg*2;
            float v[4];
            #pragma unroll
            for (int q = 0; q < 4; q++) {
                float x = acc[mi][nj][q];
                if (HASBIAS) x += bias[c0 + (q & 1)];
                if (ACT == 1) x = tanhf(x);
                else if (ACT == 2) x = 0.5f * x * (1.0f + erff(x * 0.70710678f));
                v[q] = x;
            }
            if (PL == 2) {
                #pragma unroll
                for (int h2 = 0; h2 < 2; h2++) {
                    int r = r0 + h2*8;
                    __half h0, h1, l0, l1;
                    split1h(v[2*h2], h0, l0);
                    split1h(v[2*h2+1], h1, l1);
                    __half2 hh; hh.x = h0; hh.y = h1;
                    __half2 ll; ll.x = l0; ll.y = l1;
                    *(__half2*)&outH[(size_t)r*N + c0] = hh;
                    *(__half2*)&outL[(size_t)r*N + c0] = ll;
                }
            } else if (PL == 1) {
                #pragma unroll
                for (int h2 = 0; h2 < 2; h2++) {
                    int r = r0 + h2*8;
                    __half2 hh;
                    hh.x = __float2half_rn(v[2*h2]);
                    hh.y = __float2half_rn(v[2*h2+1]);
                    *(__half2*)&outH[(size_t)r*N + c0] = hh;
                }
            } else {
                #pragma unroll
                for (int q = 0; q < 4; q++) {
                    int r = r0 + (q >> 1) * 8, c = c0 + (q & 1);
                    float x = v[q];
                    if (HASRES) x += res[(size_t)r * N + c];
                    out[(size_t)r * N + c] = x;
                }
            }
        }
}

// ---------------- LayerNorm -> fp16 planes (lo optional) ----------------
__global__ __launch_bounds__(256) void ln_kernel(
    const float* __restrict__ x, const float* __restrict__ g,
    const float* __restrict__ b, __half* __restrict__ oh,
    __half* __restrict__ ol, int gather)
{
    int row = blockIdx.x;
    int src = gather ? ((row / Tt) * Lseq + 2 * (row % Tt) + 1) : row;
    float4 v = ((const float4*)(x + (size_t)src * Cc))[threadIdx.x];
    float s = v.x + v.y + v.z + v.w;
    float q = v.x*v.x + v.y*v.y + v.z*v.z + v.w*v.w;
    #pragma unroll
    for (int o = 16; o; o >>= 1) {
        s += __shfl_xor_sync(0xffffffffu, s, o);
        q += __shfl_xor_sync(0xffffffffu, q, o);
    }
    __shared__ float ss[8], sq[8];
    int w = threadIdx.x >> 5;
    if ((threadIdx.x & 31) == 0) { ss[w] = s; sq[w] = q; }
    __syncthreads();
    s = 0.f; q = 0.f;
    #pragma unroll
    for (int i = 0; i < 8; i++) { s += ss[i]; q += sq[i]; }
    float mean = s * (1.0f / Cc);
    float rstd = rsqrtf(q * (1.0f / Cc) - mean * mean + 1e-5f);
    float4 gv = ((const float4*)g)[threadIdx.x];
    float4 bv = ((const float4*)b)[threadIdx.x];
    float o4[4];
    o4[0] = (v.x - mean) * rstd * gv.x + bv.x;
    o4[1] = (v.y - mean) * rstd * gv.y + bv.y;
    o4[2] = (v.z - mean) * rstd * gv.z + bv.z;
    o4[3] = (v.w - mean) * rstd * gv.w + bv.w;
    size_t base = (size_t)row * Cc + threadIdx.x * 4;
    __half h[4], l[4];
    #pragma unroll
    for (int e = 0; e < 4; e++) split1h(o4[e], h[e], l[e]);
    __half2 p;
    p.x=h[0]; p.y=h[1]; *(__half2*)&oh[base]   = p;
    p.x=h[2]; p.y=h[3]; *(__half2*)&oh[base+2] = p;
    if (ol) {
        p.x=l[0]; p.y=l[1]; *(__half2*)&ol[base]   = p;
        p.x=l[2]; p.y=l[3]; *(__half2*)&ol[base+2] = p;
    }
}

// ---------------- token assembly ----------------
__global__ __launch_bounds__(256) void assemble_kernel(
    const float* __restrict__ SE, const int* __restrict__ actions,
    const int* __restrict__ tsteps, const float* __restrict__ act_table,
    const float* __restrict__ pos_emb, const float* __restrict__ gpe_table,
    float* __restrict__ x)
{
    int bt = blockIdx.x;
    int b = bt / Tt, t = bt % Tt;
    int a = actions[bt];
    int ts = tsteps[bt];
    size_t row0 = (size_t)(b * Lseq + 2*t) * Cc;
    for (int c = threadIdx.x; c < Cc; c += 256) {
        float gp = gpe_table[(size_t)ts * Cc + c];
        x[row0 + c]      = SE[(size_t)bt * Cc + c] + gp + pos_emb[(size_t)(2*t) * Cc + c];
        x[row0 + Cc + c] = tanhf(act_table[(size_t)a * Cc + c]) + gp + pos_emb[(size_t)(2*t+1) * Cc + c];
    }
}

// ---------------- MMA flash attention (fp16 2-term Q/P), fused QKV input ----------------
// Output: hi plane only (WO GEMM is 1-term).
__global__ __launch_bounds__(128) void attn_kernel(
    const __half* __restrict__ QKVH, const __half* __restrict__ QKVL,
    __half* __restrict__ OutH)
{
    extern __shared__ __half smb[];
    __half* sQH = smb;
    __half* sQL = smb + 4608;
    __half* sKH = smb + 2*4608;
    __half* sVH = smb + 3*4608;

    int tid = threadIdx.x, lane = tid & 31, wid = tid >> 5;
    int b = blockIdx.y >> 4, h = blockIdx.y & 15;
    int q0 = blockIdx.x * 64;
    size_t gbase = (size_t)b * Lseq * 3072 + h * 64;

    #pragma unroll
    for (int i = 0; i < 8; i++) {
        int id = tid + i*128;
        int pl = id >> 9;
        int r = (id >> 3) & 63;
        int c = (id & 7) << 3;
        cpa16((pl ? sQL : sQH) + r*72 + c,
              (pl ? QKVL : QKVH) + gbase + (size_t)(q0 + r)*3072 + c);
    }
    asm volatile("cp.async.commit_group;" ::: "memory");

    float m0 = -1e30f, m1 = -1e30f, lsum0 = 0.f, lsum1 = 0.f;
    float O[8][4];
    #pragma unroll
    for (int f = 0; f < 8; f++)
        #pragma unroll
        for (int q = 0; q < 4; q++) O[f][q] = 0.f;

    int g = lane >> 2, tg = lane & 3;
    int wq = wid * 16;
    int row0 = q0 + wq + g, row1 = row0 + 8;
    int ntiles = blockIdx.x + 1;

    for (int kt = 0; kt < ntiles; kt++) {
        int j0 = kt * 64;
        #pragma unroll
        for (int i = 0; i < 8; i++) {
            int id = tid + i*128;
            int pl = id >> 9;                 // 0: K, 1: V
            int r = (id >> 3) & 63;
            int c = (id & 7) << 3;
            const __half* src = QKVH + gbase + (size_t)(j0 + r)*3072 + (pl ? 2048 : 1024) + c;
            __half* dst = (pl ? sVH : sKH) + r*72 + c;
            cpa16(dst, src);
        }
        asm volatile("cp.async.commit_group;" ::: "memory");
        asm volatile("cp.async.wait_group 0;" ::: "memory");
        __syncthreads();

        float S[8][4];
        #pragma unroll
        for (int f = 0; f < 8; f++)
            #pragma unroll
            for (int q = 0; q < 4; q++) S[f][q] = 0.f;

        #pragma unroll
        for (int ks = 0; ks < 4; ks++) {
            int arow = wq + (lane & 15);
            int acol = ks*16 + ((lane >> 4) << 3);
            uint32_t aH[4], aL[4];
            ldsm4(aH, sQH + arow*72 + acol);
            ldsm4(aL, sQL + arow*72 + acol);
            #pragma unroll
            for (int nb = 0; nb < 4; nb++) {
                int nr = nb*16 + ((lane >> 4) << 3) + (lane & 7);
                int kc = ks*16 + (((lane >> 3) & 1) << 3);
                uint32_t tK[4];
                ldsm4(tK, sKH + nr*72 + kc);
                uint32_t b0[2] = {tK[0], tK[1]}, b1[2] = {tK[2], tK[3]};
                mma_f16(S[2*nb],   aH, b0);
                mma_f16(S[2*nb],   aL, b0);
                mma_f16(S[2*nb+1], aH, b1);
                mma_f16(S[2*nb+1], aL, b1);
            }
        }

        #pragma unroll
        for (int f = 0; f < 8; f++) {
            int kcol = j0 + f*8 + tg*2;
            float v0 = S[f][0]*0.125f; if (kcol   > row0) v0 = -1e30f;
            float v1 = S[f][1]*0.125f; if (kcol+1 > row0) v1 = -1e30f;
            float v2 = S[f][2]*0.125f; if (kcol   > row1) v2 = -1e30f;
            float v3 = S[f][3]*0.125f; if (kcol+1 > row1) v3 = -1e30f;
            S[f][0] = v0; S[f][1] = v1; S[f][2] = v2; S[f][3] = v3;
        }
        float r0m = -1e30f, r1m = -1e30f;
        #pragma unroll
        for (int f = 0; f < 8; f++) {
            r0m = fmaxf(r0m, fmaxf(S[f][0], S[f][1]));
            r1m = fmaxf(r1m, fmaxf(S[f][2], S[f][3]));
        }
        r0m = fmaxf(r0m, __shfl_xor_sync(0xffffffffu, r0m, 1));
        r0m = fmaxf(r0m, __shfl_xor_sync(0xffffffffu, r0m, 2));
        r1m = fmaxf(r1m, __shfl_xor_sync(0xffffffffu, r1m, 1));
        r1m = fmaxf(r1m, __shfl_xor_sync(0xffffffffu, r1m, 2));
        float mn0 = fmaxf(m0, r0m), mn1 = fmaxf(m1, r1m);
        float a0 = fast_exp(m0 - mn0), a1 = fast_exp(m1 - mn1);
        m0 = mn0; m1 = mn1;

        float s0 = 0.f, s1 = 0.f;
        #pragma unroll
        for (int f = 0; f < 8; f++) {
            float p0 = fast_exp(S[f][0] - mn0);
            float p1 = fast_exp(S[f][1] - mn0);
            float p2 = fast_exp(S[f][2] - mn1);
            float p3 = fast_exp(S[f][3] - mn1);
            S[f][0] = p0; S[f][1] = p1; S[f][2] = p2; S[f][3] = p3;
            s0 += p0 + p1; s1 += p2 + p3;
        }
        s0 += __shfl_xor_sync(0xffffffffu, s0, 1);
        s0 += __shfl_xor_sync(0xffffffffu, s0, 2);
        s1 += __shfl_xor_sync(0xffffffffu, s1, 1);
        s1 += __shfl_xor_sync(0xffffffffu, s1, 2);
        lsum0 = lsum0 * a0 + s0;
        lsum1 = lsum1 * a1 + s1;
        #pragma unroll
        for (int f = 0; f < 8; f++) {
            O[f][0] *= a0; O[f][1] *= a0;
            O[f][2] *= a1; O[f][3] *= a1;
        }

        #pragma unroll
        for (int ks2 = 0; ks2 < 4; ks2++) {
            uint32_t pH[4], pL[4];
            #pragma unroll
            for (int hf = 0; hf < 2; hf++) {
                int f = 2*ks2 + hf;
                __half h0,h1,h2,h3,l0,l1,l2,l3;
                split1h(S[f][0], h0, l0); split1h(S[f][1], h1, l1);
                split1h(S[f][2], h2, l2); split1h(S[f][3], h3, l3);
                __half2 t;
                t.x=h0; t.y=h1; pH[hf*2+0] = *(uint32_t*)&t;
                t.x=h2; t.y=h3; pH[hf*2+1] = *(uint32_t*)&t;
                t.x=l0; t.y=l1; pL[hf*2+0] = *(uint32_t*)&t;
                t.x=l2; t.y=l3; pL[hf*2+1] = *(uint32_t*)&t;
            }
            int vrow = ks2*16 + (lane & 15);
            #pragma unroll
            for (int nb = 0; nb < 4; nb++) {
                int vcol = nb*16 + ((lane >> 4) << 3);
                uint32_t tV[4];
                ldsm4t(tV, sVH + vrow*72 + vcol);
                uint32_t b0[2] = {tV[0], tV[1]}, b1[2] = {tV[2], tV[3]};
                mma_f16(O[2*nb],   pH, b0);
                mma_f16(O[2*nb],   pL, b0);
                mma_f16(O[2*nb+1], pH, b1);
                mma_f16(O[2*nb+1], pL, b1);
            }
        }
        __syncthreads();
    }

    float rl0 = 1.f / lsum0, rl1 = 1.f / lsum1;
    size_t t0 = (size_t)(b*Lseq + row0), t1 = (size_t)(b*Lseq + row1);
    #pragma unroll
    for (int f = 0; f < 8; f++) {
        int gcol = h*64 + f*8 + tg*2;
        __half2 ph;
        ph.x = __float2half_rn(O[f][0]*rl0);
        ph.y = __float2half_rn(O[f][1]*rl0);
        *(__half2*)&OutH[t0*Cc + gcol] = ph;
        ph.x = __float2half_rn(O[f][2]*rl1);
        ph.y = __float2half_rn(O[f][3]*rl1);
        *(__half2*)&OutH[t1*Cc + gcol] = ph;
    }
}

// ---------------- batched weight transpose + fp16 ----------------
__global__ __launch_bounds__(256) void wsplit_kernel(
    const float* __restrict__ W, __half* __restrict__ Wh, int K, int N,
    size_t inStride, size_t outStride)
{
    const float* Wz = W + (size_t)blockIdx.z * inStride;
    __half* Whz = Wh + (size_t)blockIdx.z * outStride;
    __shared__ float tile[32][33];
    int k0 = blockIdx.y * 32, n0 = blockIdx.x * 32;
    int tx = threadIdx.x & 31, ty = threadIdx.x >> 5;
    #pragma unroll
    for (int r = ty; r < 32; r += 8)
        tile[r][tx] = Wz[(size_t)(k0 + r) * N + n0 + tx];
    __syncthreads();
    #pragma unroll
    for (int r = ty; r < 32; r += 8)
        Whz[(size_t)(n0 + r) * K + k0 + tx] = __float2half_rn(tile[tx][r]);
}

// ---------------- fused QKV bias concat ----------------
__global__ __launch_bounds__(256) void bcat_kernel(
    const float* __restrict__ bq, const float* __restrict__ bk,
    const float* __restrict__ bv, float* __restrict__ outb)
{
    int i = blockIdx.x * 256 + threadIdx.x;
    if (i < NLAYER * 3072) {
        int lyr = i / 3072, c = i % 3072;
        float v = (c < 1024) ? bq[lyr*1024 + c]
                : (c < 2048) ? bk[lyr*1024 + c - 1024]
                             : bv[lyr*1024 + c - 2048];
        outb[i] = v;
    }
}

// ---------------- elementwise 2-plane split (states) ----------------
__global__ __launch_bounds__(256) void esplit_kernel(
    const float* __restrict__ x, __half* __restrict__ h,
    __half* __restrict__ l, int n)
{
    int i = (blockIdx.x * 256 + threadIdx.x) * 4;
    if (i < n) {
        float4 v = *(const float4*)&x[i];
        float a[4] = {v.x, v.y, v.z, v.w};
        __half hh[4], ll[4];
        #pragma unroll
        for (int e = 0; e < 4; e++) split1h(a[e], hh[e], ll[e]);
        __half2 p;
        p.x=hh[0]; p.y=hh[1]; *(__half2*)&h[i]   = p;
        p.x=hh[2]; p.y=hh[3]; *(__half2*)&h[i+2] = p;
        p.x=ll[0]; p.y=ll[1]; *(__half2*)&l[i]   = p;
        p.x=ll[2]; p.y=ll[3]; *(__half2*)&l[i+2] = p;
    }
}

// ---------------- launcher ----------------
extern "C" void kernel_launch(void* const* d_in, const int* in_sizes, int n_in,
                              void* d_out, int out_size) {
    const float* states   = (const float*)d_in[0];
    const int*   actions  = (const int*)d_in[1];
    const int*   tsteps   = (const int*)d_in[2];
    const float* W_se     = (const float*)d_in[3];
    const float* b_se     = (const float*)d_in[4];
    const float* act_tab  = (const float*)d_in[5];
    const float* pos_emb  = (const float*)d_in[6];
    const float* gpe      = (const float*)d_in[7];
    const float* ln1_g    = (const float*)d_in[8];
    const float* ln1_b    = (const float*)d_in[9];
    const float* Wq       = (const float*)d_in[10];
    const float* bq       = (const float*)d_in[11];
    const float* Wk       = (const float*)d_in[12];
    const float* bk       = (const float*)d_in[13];
    const float* Wv       = (const float*)d_in[14];
    const float* bv       = (const float*)d_in[15];
    const float* Wo       = (const float*)d_in[16];
    const float* bo       = (const float*)d_in[17];
    const float* ln2_g    = (const float*)d_in[18];
    const float* ln2_b    = (const float*)d_in[19];
    const float* W1       = (const float*)d_in[20];
    const float* b1       = (const float*)d_in[21];
    const float* W2       = (const float*)d_in[22];
    const float* b2       = (const float*)d_in[23];
    const float* lnf_g    = (const float*)d_in[24];
    const float* lnf_b    = (const float*)d_in[25];
    const float* W_head   = (const float*)d_in[26];
    float* out = (float*)d_out;

    float* F = nullptr;
    cudaGetSymbolAddress((void**)&F, g_f32);
    float* BQKV = nullptr;
    cudaGetSymbolAddress((void**)&BQKV, g_bqkv);
    __half* HP = nullptr;
    cudaGetSymbolAddress((void**)&HP, g_hp);

    float* X  = F;
    float* X2 = X  + N_BLC;
    float* HF = X2 + N_BLC;

    size_t off = 0;
    auto take = [&](size_t n) { __half* p = HP + off; off += n; return p; };
    __half *stH = take(524288), *stL = take(524288);
    __half *wseH = take(131072);
    __half *wAll = take(67108864);     // per layer: [qkv 3.1M][wo 1.0M][w1 2.1M][w2 2.1M]
    __half *hdH = take(4194304);
    __half *HbH = take(N_BLC);
    __half *AOH = take(N_BLC);
    __half *MIDH = take(2*N_BLC);
    __half *HFH = take(N_HF);
    __half *QKVH = take(3*N_BLC), *QKVL = take(3*N_BLC);

    const size_t LW = 8388608;          // per-layer weight stride (halves)
    const size_t OFF_QKV = 0, OFF_WO = 3145728, OFF_W1 = 4194304, OFF_W2 = 6291456;

    const int GSM2 = 3*3*5120*2;        // 92160 B (3 stages, 3 tiles)
    const int GSM1 = 3*2*5120*2;        // 61440 B (3 stages, 2 tiles)
    const int ATSM = 4*4608*2;          // 36864 B
    cudaFuncSetAttribute(gemm_hk<1,true,false,0,2>, cudaFuncAttributeMaxDynamicSharedMemorySize, GSM2);
    cudaFuncSetAttribute(gemm_hk<0,true,false,2,1>, cudaFuncAttributeMaxDynamicSharedMemorySize, GSM1);
    cudaFuncSetAttribute(gemm_hk<0,true,true,0,1>,  cudaFuncAttributeMaxDynamicSharedMemorySize, GSM1);
    cudaFuncSetAttribute(gemm_hk<2,true,false,1,1>, cudaFuncAttributeMaxDynamicSharedMemorySize, GSM1);
    cudaFuncSetAttribute(gemm_hk<0,false,false,0,1>,cudaFuncAttributeMaxDynamicSharedMemorySize, GSM1);
    cudaFuncSetAttribute(attn_kernel, cudaFuncAttributeMaxDynamicSharedMemorySize, ATSM);

    const int Mx = Bb * Lseq;   // 8192
    const int Mh = Bb * Tt;     // 4096
    dim3 thr(256);

    // ---- prep (batched) ----
    esplit_kernel<<<512, thr>>>(states, stH, stL, Mh * Ss);
    bcat_kernel<<<96, thr>>>(bq, bk, bv, BQKV);
    wsplit_kernel<<<dim3(Cc/32, Ss/32, 1), thr>>>(W_se, wseH, Ss, Cc, 0, 0);
    wsplit_kernel<<<dim3(Cc/32, Cc/32, NLAYER), thr>>>(Wq, wAll + OFF_QKV,            Cc, Cc,   (size_t)Cc*Cc,   LW);
    wsplit_kernel<<<dim3(Cc/32, Cc/32, NLAYER), thr>>>(Wk, wAll + OFF_QKV + 1024*Cc,  Cc, Cc,   (size_t)Cc*Cc,   LW);
    wsplit_kernel<<<dim3(Cc/32, Cc/32, NLAYER), thr>>>(Wv, wAll + OFF_QKV + 2048*Cc,  Cc, Cc,   (size_t)Cc*Cc,   LW);
    wsplit_kernel<<<dim3(Cc/32, Cc/32, NLAYER), thr>>>(Wo, wAll + OFF_WO,             Cc, Cc,   (size_t)Cc*Cc,   LW);
    wsplit_kernel<<<dim3(2*Cc/32, Cc/32, NLAYER), thr>>>(W1, wAll + OFF_W1,           Cc, 2*Cc, (size_t)2*Cc*Cc, LW);
    wsplit_kernel<<<dim3(Cc/32, 2*Cc/32, NLAYER), thr>>>(W2, wAll + OFF_W2,           2*Cc, Cc, (size_t)2*Cc*Cc, LW);
    wsplit_kernel<<<dim3(VOC/32, Cc/32, 1), thr>>>(W_head, hdH, Cc, VOC, 0, 0);

    // ---- state encoder + token assembly ----
    gemm_hk<1,true,false,0,2><<<dim3(Cc/128, Mh/128), thr, GSM2>>>(
        stH, stL, wseH, b_se, nullptr, HF, nullptr, nullptr, Mh, Cc, Ss);
    assemble_kernel<<<Mh, thr>>>(HF, actions, tsteps, act_tab, pos_emb, gpe, X);

    for (int lyr = 0; lyr < NLAYER; lyr++) {
        __half* wqkv = wAll + lyr*LW + OFF_QKV;
        __half* wo   = wAll + lyr*LW + OFF_WO;
        __half* w1   = wAll + lyr*LW + OFF_W1;
        __half* w2   = wAll + lyr*LW + OFF_W2;

        ln_kernel<<<Mx, thr>>>(X, ln1_g + lyr*Cc, ln1_b + lyr*Cc, HbH, nullptr, 0);
        gemm_hk<0,true,false,2,1><<<dim3(3072/128, Mx/128), thr, GSM1>>>(
            HbH, nullptr, wqkv, BQKV + lyr*3072, nullptr, nullptr, QKVH, QKVL, Mx, 3072, Cc);
        attn_kernel<<<dim3(Lseq/64, Bb*16), dim3(128), ATSM>>>(QKVH, QKVL, AOH);
        gemm_hk<0,true,true,0,1><<<dim3(Cc/128, Mx/128), thr, GSM1>>>(
            AOH, nullptr, wo, bo + lyr*Cc, X, X2, nullptr, nullptr, Mx, Cc, Cc);
        ln_kernel<<<Mx, thr>>>(X2, ln2_g + lyr*Cc, ln2_b + lyr*Cc, HbH, nullptr, 0);
        gemm_hk<2,true,false,1,1><<<dim3(2*Cc/128, Mx/128), thr, GSM1>>>(
            HbH, nullptr, w1, b1 + lyr*2*Cc, nullptr, nullptr, MIDH, nullptr, Mx, 2*Cc, Cc);
        gemm_hk<0,true,true,0,1><<<dim3(Cc/128, Mx/128), thr, GSM1>>>(
            MIDH, nullptr, w2, b2 + lyr*Cc, X2, X, nullptr, nullptr, Mx, Cc, 2*Cc);
    }

    ln_kernel<<<Mh, thr>>>(X, lnf_g, lnf_b, HFH, nullptr, 1);
    gemm_hk<0,false,false,0,1><<<dim3(VOC/128, Mh/128), thr, GSM1>>>(
        HFH, nullptr, hdH, nullptr, nullptr, out, nullptr, nullptr, Mh, VOC, Cc);
}

// round 11
// speedup vs baseline: 1.7541x; 1.1140x over previous
#include <cuda_runtime.h>
#include <cuda_fp16.h>
#include <cstdint>

#define Bb 4
#define Tt 1024
#define Ss 128
#define Cc 1024
#define NLAYER 8
#define VOC 4096
#define Lseq 2048

#define N_BLC (Bb*Lseq*Cc)
#define N_HF  (Bb*Tt*Cc)

__device__ float g_f32[2*N_BLC + N_HF];       // X, X2, HF
__device__ float g_bqkv[NLAYER*3072];         // fused qkv bias
__device__ __half g_hp[198311936];            // all fp16 planes

#define LWs 8388608u
#define OFF_QKVs 0u
#define OFF_WOs 3145728u
#define OFF_W1s 4194304u
#define OFF_W2s 6291456u

// ---------------- helpers ----------------
__device__ __forceinline__ void ldsm4(uint32_t r[4], const __half* p) {
    uint32_t a = (uint32_t)__cvta_generic_to_shared(p);
    asm volatile("ldmatrix.sync.aligned.m8n8.x4.shared.b16 {%0,%1,%2,%3}, [%4];"
        : "=r"(r[0]), "=r"(r[1]), "=r"(r[2]), "=r"(r[3]) : "r"(a));
}
__device__ __forceinline__ void ldsm4t(uint32_t r[4], const __half* p) {
    uint32_t a = (uint32_t)__cvta_generic_to_shared(p);
    asm volatile("ldmatrix.sync.aligned.m8n8.x4.trans.shared.b16 {%0,%1,%2,%3}, [%4];"
        : "=r"(r[0]), "=r"(r[1]), "=r"(r[2]), "=r"(r[3]) : "r"(a));
}
__device__ __forceinline__ void mma_f16(float c[4], const uint32_t a[4], const uint32_t b[2]) {
    asm volatile("mma.sync.aligned.m16n8k16.row.col.f32.f16.f16.f32 "
        "{%0,%1,%2,%3}, {%4,%5,%6,%7}, {%8,%9}, {%0,%1,%2,%3};"
        : "+f"(c[0]), "+f"(c[1]), "+f"(c[2]), "+f"(c[3])
        : "r"(a[0]), "r"(a[1]), "r"(a[2]), "r"(a[3]), "r"(b[0]), "r"(b[1]));
}
__device__ __forceinline__ void cpa16(__half* dst, const __half* src) {
    uint32_t d = (uint32_t)__cvta_generic_to_shared(dst);
    asm volatile("cp.async.cg.shared.global [%0], [%1], 16;" :: "r"(d), "l"(src));
}
__device__ __forceinline__ void split1h(float v, __half& h, __half& l) {
    h = __float2half_rn(v);
    l = __float2half_rn(v - __half2float(h));
}
__device__ __forceinline__ float fast_exp(float x) {
    x = fmaxf(x, -80.f);
    float y = x * 1.44269504088896f;
    float t = y + 12582912.f;
    int ni = __float_as_int(t) - 0x4B400000;
    float f = y - (t - 12582912.f);
    float p = 1.33335581e-3f;
    p = fmaf(p, f, 9.61812910e-3f);
    p = fmaf(p, f, 5.55041087e-2f);
    p = fmaf(p, f, 2.40226507e-1f);
    p = fmaf(p, f, 6.93147180e-1f);
    p = fmaf(p, f, 1.0f);
    return p * __int_as_float((ni + 127) << 23);
}

// ---------------- GEMM: out = act((Ah[+Al])@W16^T + bias)(+res) ----------------
template<int ACT, bool HASBIAS, bool HASRES, int PL, int TERMS>
__global__ __launch_bounds__(256, 2) void gemm_hk(
    const __half* __restrict__ Ah, const __half* __restrict__ Al,
    const __half* __restrict__ Wh,
    const float* __restrict__ bias, const float* __restrict__ res,
    float* __restrict__ out, __half* __restrict__ outH, __half* __restrict__ outL,
    int M, int N, int K)
{
    extern __shared__ __half sm[];
    const int TILE = 128*40;
    const int STH = (1 + TERMS) * TILE;
    int tid = threadIdx.x, lane = tid & 31, warp = tid >> 5;
    int bm = blockIdx.y * 128, bn = blockIdx.x * 128;
    int wm = (warp >> 1) * 32, wn = (warp & 1) * 64;

    float acc[2][8][4];
    #pragma unroll
    for (int i = 0; i < 2; i++)
        #pragma unroll
        for (int j = 0; j < 8; j++)
            #pragma unroll
            for (int q = 0; q < 4; q++) acc[i][j][q] = 0.f;

    int niter = K >> 5;

    #define ISSUE(ST, K0) do {                                                  \
        int _k0 = (K0);                                                         \
        _Pragma("unroll")                                                       \
        for (int _i = 0; _i < 2*(1+TERMS); _i++) {                              \
            int _id = tid + (_i << 8);                                          \
            int _tile = _id >> 9;                                               \
            int _r = (_id >> 2) & 127;                                          \
            int _c = (_id & 3) << 3;                                            \
            const __half* _src =                                                \
                (_tile == 0) ? Ah + (size_t)(bm + _r) * K + _k0 + _c :          \
                (TERMS == 2 && _tile == 1) ? Al + (size_t)(bm + _r) * K + _k0 + _c : \
                               Wh + (size_t)(bn + _r) * K + _k0 + _c;           \
            cpa16(sm + (ST)*STH + _tile*TILE + _r*40 + _c, _src);               \
        }                                                                       \
        asm volatile("cp.async.commit_group;" ::: "memory");                    \
    } while (0)

    ISSUE(0, 0);
    if (niter > 1) ISSUE(1, 32);
    for (int it = 0; it < niter; ++it) {
        if (it + 1 < niter) {
            asm volatile("cp.async.wait_group 1;" ::: "memory");
        } else {
            asm volatile("cp.async.wait_group 0;" ::: "memory");
        }
        __syncthreads();
        if (it + 2 < niter) ISSUE((it + 2) % 3, (it + 2) << 5);

        int st = it % 3;
        const __half* AshH = sm + st*STH;
        const __half* AshL = AshH + TILE;
        const __half* BshW = AshH + TERMS*TILE;

        #pragma unroll
        for (int ks = 0; ks < 2; ks++) {
            uint32_t aH[2][4], aL[2][4];
            #pragma unroll
            for (int mi = 0; mi < 2; mi++) {
                int row = wm + mi*16 + (lane & 15);
                int col = ks*16 + ((lane >> 4) << 3);
                ldsm4(aH[mi], &AshH[row*40 + col]);
                if (TERMS == 2) ldsm4(aL[mi], &AshL[row*40 + col]);
            }
            uint32_t bW[8][2];
            #pragma unroll
            for (int pi = 0; pi < 4; pi++) {
                int nr = wn + pi*16 + ((lane >> 4) << 3) + (lane & 7);
                int kc = ks*16 + (((lane >> 3) & 1) << 3);
                uint32_t t[4];
                ldsm4(t, &BshW[nr*40 + kc]);
                bW[2*pi][0] = t[0]; bW[2*pi][1] = t[1];
                bW[2*pi+1][0] = t[2]; bW[2*pi+1][1] = t[3];
            }
            #pragma unroll
            for (int mi = 0; mi < 2; mi++)
                #pragma unroll
                for (int nj = 0; nj < 8; nj++) {
                    mma_f16(acc[mi][nj], aH[mi], bW[nj]);
                    if (TERMS == 2) mma_f16(acc[mi][nj], aL[mi], bW[nj]);
                }
        }
    }
    #undef ISSUE

    int g = lane >> 2, tg = lane & 3;
    #pragma unroll
    for (int mi = 0; mi < 2; mi++)
        #pragma unroll
        for (int nj = 0; nj < 8; nj++) {
            int r0 = bm + wm + mi*16 + g;
            int c0 = bn + wn + nj*8 + tg*2;
            float v[4];
            #pragma unroll
            for (int q = 0; q < 4; q++) {
                float x = acc[mi][nj][q];
                if (HASBIAS) x += bias[c0 + (q & 1)];
                if (ACT == 1) x = tanhf(x);
                else if (ACT == 2) x = 0.5f * x * (1.0f + erff(x * 0.70710678f));
                v[q] = x;
            }
            if (PL == 2) {
                #pragma unroll
                for (int h2 = 0; h2 < 2; h2++) {
                    int r = r0 + h2*8;
                    __half h0, h1, l0, l1;
                    split1h(v[2*h2], h0, l0);
                    split1h(v[2*h2+1], h1, l1);
                    __half2 hh; hh.x = h0; hh.y = h1;
                    __half2 ll; ll.x = l0; ll.y = l1;
                    *(__half2*)&outH[(size_t)r*N + c0] = hh;
                    *(__half2*)&outL[(size_t)r*N + c0] = ll;
                }
            } else if (PL == 1) {
                #pragma unroll
                for (int h2 = 0; h2 < 2; h2++) {
                    int r = r0 + h2*8;
                    __half2 hh;
                    hh.x = __float2half_rn(v[2*h2]);
                    hh.y = __float2half_rn(v[2*h2+1]);
                    *(__half2*)&outH[(size_t)r*N + c0] = hh;
                }
            } else {
                #pragma unroll
                for (int q = 0; q < 4; q++) {
                    int r = r0 + (q >> 1) * 8, c = c0 + (q & 1);
                    float x = v[q];
                    if (HASRES) x += res[(size_t)r * N + c];
                    out[(size_t)r * N + c] = x;
                }
            }
        }
}

// ---------------- LayerNorm -> fp16 planes (lo optional) ----------------
__global__ __launch_bounds__(256) void ln_kernel(
    const float* __restrict__ x, const float* __restrict__ g,
    const float* __restrict__ b, __half* __restrict__ oh,
    __half* __restrict__ ol, int gather)
{
    int row = blockIdx.x;
    int src = gather ? ((row / Tt) * Lseq + 2 * (row % Tt) + 1) : row;
    float4 v = ((const float4*)(x + (size_t)src * Cc))[threadIdx.x];
    float s = v.x + v.y + v.z + v.w;
    float q = v.x*v.x + v.y*v.y + v.z*v.z + v.w*v.w;
    #pragma unroll
    for (int o = 16; o; o >>= 1) {
        s += __shfl_xor_sync(0xffffffffu, s, o);
        q += __shfl_xor_sync(0xffffffffu, q, o);
    }
    __shared__ float ss[8], sq[8];
    int w = threadIdx.x >> 5;
    if ((threadIdx.x & 31) == 0) { ss[w] = s; sq[w] = q; }
    __syncthreads();
    s = 0.f; q = 0.f;
    #pragma unroll
    for (int i = 0; i < 8; i++) { s += ss[i]; q += sq[i]; }
    float mean = s * (1.0f / Cc);
    float rstd = rsqrtf(q * (1.0f / Cc) - mean * mean + 1e-5f);
    float4 gv = ((const float4*)g)[threadIdx.x];
    float4 bv = ((const float4*)b)[threadIdx.x];
    float o4[4];
    o4[0] = (v.x - mean) * rstd * gv.x + bv.x;
    o4[1] = (v.y - mean) * rstd * gv.y + bv.y;
    o4[2] = (v.z - mean) * rstd * gv.z + bv.z;
    o4[3] = (v.w - mean) * rstd * gv.w + bv.w;
    size_t base = (size_t)row * Cc + threadIdx.x * 4;
    __half h[4], l[4];
    #pragma unroll
    for (int e = 0; e < 4; e++) split1h(o4[e], h[e], l[e]);
    __half2 p;
    p.x=h[0]; p.y=h[1]; *(__half2*)&oh[base]   = p;
    p.x=h[2]; p.y=h[3]; *(__half2*)&oh[base+2] = p;
    if (ol) {
        p.x=l[0]; p.y=l[1]; *(__half2*)&ol[base]   = p;
        p.x=l[2]; p.y=l[3]; *(__half2*)&ol[base+2] = p;
    }
}

// ---------------- token assembly ----------------
__global__ __launch_bounds__(256) void assemble_kernel(
    const float* __restrict__ SE, const int* __restrict__ actions,
    const int* __restrict__ tsteps, const float* __restrict__ act_table,
    const float* __restrict__ pos_emb, const float* __restrict__ gpe_table,
    float* __restrict__ x)
{
    int bt = blockIdx.x;
    int b = bt / Tt, t = bt % Tt;
    int a = actions[bt];
    int ts = tsteps[bt];
    size_t row0 = (size_t)(b * Lseq + 2*t) * Cc;
    for (int c = threadIdx.x; c < Cc; c += 256) {
        float gp = gpe_table[(size_t)ts * Cc + c];
        x[row0 + c]      = SE[(size_t)bt * Cc + c] + gp + pos_emb[(size_t)(2*t) * Cc + c];
        x[row0 + Cc + c] = tanhf(act_table[(size_t)a * Cc + c]) + gp + pos_emb[(size_t)(2*t+1) * Cc + c];
    }
}

// ---------------- MMA flash attention (fp16 1-term), fused QKV input ----------------
__global__ __launch_bounds__(128) void attn_kernel(
    const __half* __restrict__ QKVH, __half* __restrict__ OutH)
{
    extern __shared__ __half smb[];
    __half* sQH = smb;
    __half* sKH = smb + 4608;
    __half* sVH = smb + 2*4608;

    int tid = threadIdx.x, lane = tid & 31, wid = tid >> 5;
    int b = blockIdx.y >> 4, h = blockIdx.y & 15;
    int q0 = blockIdx.x * 64;
    size_t gbase = (size_t)b * Lseq * 3072 + h * 64;

    #pragma unroll
    for (int i = 0; i < 4; i++) {
        int id = tid + i*128;
        int r = (id >> 3) & 63;
        int c = (id & 7) << 3;
        cpa16(sQH + r*72 + c, QKVH + gbase + (size_t)(q0 + r)*3072 + c);
    }
    asm volatile("cp.async.commit_group;" ::: "memory");

    float m0 = -1e30f, m1 = -1e30f, lsum0 = 0.f, lsum1 = 0.f;
    float O[8][4];
    #pragma unroll
    for (int f = 0; f < 8; f++)
        #pragma unroll
        for (int q = 0; q < 4; q++) O[f][q] = 0.f;

    int g = lane >> 2, tg = lane & 3;
    int wq = wid * 16;
    int row0 = q0 + wq + g, row1 = row0 + 8;
    int ntiles = blockIdx.x + 1;

    for (int kt = 0; kt < ntiles; kt++) {
        int j0 = kt * 64;
        #pragma unroll
        for (int i = 0; i < 8; i++) {
            int id = tid + i*128;
            int pl = id >> 9;                 // 0: K, 1: V
            int r = (id >> 3) & 63;
            int c = (id & 7) << 3;
            const __half* src = QKVH + gbase + (size_t)(j0 + r)*3072 + (pl ? 2048 : 1024) + c;
            __half* dst = (pl ? sVH : sKH) + r*72 + c;
            cpa16(dst, src);
        }
        asm volatile("cp.async.commit_group;" ::: "memory");
        asm volatile("cp.async.wait_group 0;" ::: "memory");
        __syncthreads();

        float S[8][4];
        #pragma unroll
        for (int f = 0; f < 8; f++)
            #pragma unroll
            for (int q = 0; q < 4; q++) S[f][q] = 0.f;

        #pragma unroll
        for (int ks = 0; ks < 4; ks++) {
            int arow = wq + (lane & 15);
            int acol = ks*16 + ((lane >> 4) << 3);
            uint32_t aH[4];
            ldsm4(aH, sQH + arow*72 + acol);
            #pragma unroll
            for (int nb = 0; nb < 4; nb++) {
                int nr = nb*16 + ((lane >> 4) << 3) + (lane & 7);
                int kc = ks*16 + (((lane >> 3) & 1) << 3);
                uint32_t tK[4];
                ldsm4(tK, sKH + nr*72 + kc);
                uint32_t b0[2] = {tK[0], tK[1]}, b1[2] = {tK[2], tK[3]};
                mma_f16(S[2*nb],   aH, b0);
                mma_f16(S[2*nb+1], aH, b1);
            }
        }

        #pragma unroll
        for (int f = 0; f < 8; f++) {
            int kcol = j0 + f*8 + tg*2;
            float v0 = S[f][0]*0.125f; if (kcol   > row0) v0 = -1e30f;
            float v1 = S[f][1]*0.125f; if (kcol+1 > row0) v1 = -1e30f;
            float v2 = S[f][2]*0.125f; if (kcol   > row1) v2 = -1e30f;
            float v3 = S[f][3]*0.125f; if (kcol+1 > row1) v3 = -1e30f;
            S[f][0] = v0; S[f][1] = v1; S[f][2] = v2; S[f][3] = v3;
        }
        float r0m = -1e30f, r1m = -1e30f;
        #pragma unroll
        for (int f = 0; f < 8; f++) {
            r0m = fmaxf(r0m, fmaxf(S[f][0], S[f][1]));
            r1m = fmaxf(r1m, fmaxf(S[f][2], S[f][3]));
        }
        r0m = fmaxf(r0m, __shfl_xor_sync(0xffffffffu, r0m, 1));
        r0m = fmaxf(r0m, __shfl_xor_sync(0xffffffffu, r0m, 2));
        r1m = fmaxf(r1m, __shfl_xor_sync(0xffffffffu, r1m, 1));
        r1m = fmaxf(r1m, __shfl_xor_sync(0xffffffffu, r1m, 2));
        float mn0 = fmaxf(m0, r0m), mn1 = fmaxf(m1, r1m);
        float a0 = fast_exp(m0 - mn0), a1 = fast_exp(m1 - mn1);
        m0 = mn0; m1 = mn1;

        float s0 = 0.f, s1 = 0.f;
        #pragma unroll
        for (int f = 0; f < 8; f++) {
            float p0 = fast_exp(S[f][0] - mn0);
            float p1 = fast_exp(S[f][1] - mn0);
            float p2 = fast_exp(S[f][2] - mn1);
            float p3 = fast_exp(S[f][3] - mn1);
            S[f][0] = p0; S[f][1] = p1; S[f][2] = p2; S[f][3] = p3;
            s0 += p0 + p1; s1 += p2 + p3;
        }
        s0 += __shfl_xor_sync(0xffffffffu, s0, 1);
        s0 += __shfl_xor_sync(0xffffffffu, s0, 2);
        s1 += __shfl_xor_sync(0xffffffffu, s1, 1);
        s1 += __shfl_xor_sync(0xffffffffu, s1, 2);
        lsum0 = lsum0 * a0 + s0;
        lsum1 = lsum1 * a1 + s1;
        #pragma unroll
        for (int f = 0; f < 8; f++) {
            O[f][0] *= a0; O[f][1] *= a0;
            O[f][2] *= a1; O[f][3] *= a1;
        }

        #pragma unroll
        for (int ks2 = 0; ks2 < 4; ks2++) {
            uint32_t pH[4];
            #pragma unroll
            for (int hf = 0; hf < 2; hf++) {
                int f = 2*ks2 + hf;
                __half2 t;
                t.x = __float2half_rn(S[f][0]);
                t.y = __float2half_rn(S[f][1]);
                pH[hf*2+0] = *(uint32_t*)&t;
                t.x = __float2half_rn(S[f][2]);
                t.y = __float2half_rn(S[f][3]);
                pH[hf*2+1] = *(uint32_t*)&t;
            }
            int vrow = ks2*16 + (lane & 15);
            #pragma unroll
            for (int nb = 0; nb < 4; nb++) {
                int vcol = nb*16 + ((lane >> 4) << 3);
                uint32_t tV[4];
                ldsm4t(tV, sVH + vrow*72 + vcol);
                uint32_t b0[2] = {tV[0], tV[1]}, b1[2] = {tV[2], tV[3]};
                mma_f16(O[2*nb],   pH, b0);
                mma_f16(O[2*nb+1], pH, b1);
            }
        }
        __syncthreads();
    }

    float rl0 = 1.f / lsum0, rl1 = 1.f / lsum1;
    size_t t0 = (size_t)(b*Lseq + row0), t1 = (size_t)(b*Lseq + row1);
    #pragma unroll
    for (int f = 0; f < 8; f++) {
        int gcol = h*64 + f*8 + tg*2;
        __half2 ph;
        ph.x = __float2half_rn(O[f][0]*rl0);
        ph.y = __float2half_rn(O[f][1]*rl0);
        *(__half2*)&OutH[t0*Cc + gcol] = ph;
        ph.x = __float2half_rn(O[f][2]*rl1);
        ph.y = __float2half_rn(O[f][3]*rl1);
        *(__half2*)&OutH[t1*Cc + gcol] = ph;
    }
}

// ---------------- weight transpose + fp16 (generic) ----------------
__global__ __launch_bounds__(256) void wsplit_kernel(
    const float* __restrict__ W, __half* __restrict__ Wh, int K, int N,
    size_t inStride, size_t outStride)
{
    const float* Wz = W + (size_t)blockIdx.z * inStride;
    __half* Whz = Wh + (size_t)blockIdx.z * outStride;
    __shared__ float tile[32][33];
    int k0 = blockIdx.y * 32, n0 = blockIdx.x * 32;
    int tx = threadIdx.x & 31, ty = threadIdx.x >> 5;
    #pragma unroll
    for (int r = ty; r < 32; r += 8)
        tile[r][tx] = Wz[(size_t)(k0 + r) * N + n0 + tx];
    __syncthreads();
    #pragma unroll
    for (int r = ty; r < 32; r += 8)
        Whz[(size_t)(n0 + r) * K + k0 + tx] = __float2half_rn(tile[tx][r]);
}

// ---------------- merged wsplit: Wq/Wk/Wv/Wo (all 1024x1024, 8 layers) ----------------
__global__ __launch_bounds__(256) void wsplit4_kernel(
    const float* __restrict__ Wq, const float* __restrict__ Wk,
    const float* __restrict__ Wv, const float* __restrict__ Wo,
    __half* __restrict__ wAll)
{
    int z = blockIdx.z;
    int m = z >> 3, lyr = z & 7;
    const float* W = (m == 0 ? Wq : m == 1 ? Wk : m == 2 ? Wv : Wo)
                   + (size_t)lyr * Cc * Cc;
    uint32_t doff = (m == 0) ? OFF_QKVs
                  : (m == 1) ? OFF_QKVs + 1024u*Cc
                  : (m == 2) ? OFF_QKVs + 2048u*Cc : OFF_WOs;
    __half* out = wAll + (size_t)lyr * LWs + doff;

    __shared__ float tile[32][33];
    int k0 = blockIdx.y * 32, n0 = blockIdx.x * 32;
    int tx = threadIdx.x & 31, ty = threadIdx.x >> 5;
    #pragma unroll
    for (int r = ty; r < 32; r += 8)
        tile[r][tx] = W[(size_t)(k0 + r) * Cc + n0 + tx];
    __syncthreads();
    #pragma unroll
    for (int r = ty; r < 32; r += 8)
        out[(size_t)(n0 + r) * Cc + k0 + tx] = __float2half_rn(tile[tx][r]);
}

// ---------------- merged wsplit: W1 (1024x2048) + W2 (2048x1024), 8 layers ----------------
__global__ __launch_bounds__(256) void wsplit12_kernel(
    const float* __restrict__ W1, const float* __restrict__ W2,
    __half* __restrict__ wAll)
{
    int z = blockIdx.z;
    int m = z >> 3, lyr = z & 7;
    int K = m ? 2048 : 1024;
    int N = m ? 1024 : 2048;
    int k0 = blockIdx.y * 32, n0 = blockIdx.x * 32;
    if (k0 >= K || n0 >= N) return;
    const float* W = (m ? W2 : W1) + (size_t)lyr * 2097152;
    __half* out = wAll + (size_t)lyr * LWs + (m ? OFF_W2s : OFF_W1s);

    __shared__ float tile[32][33];
    int tx = threadIdx.x & 31, ty = threadIdx.x >> 5;
    #pragma unroll
    for (int r = ty; r < 32; r += 8)
        tile[r][tx] = W[(size_t)(k0 + r) * N + n0 + tx];
    __syncthreads();
    #pragma unroll
    for (int r = ty; r < 32; r += 8)
        out[(size_t)(n0 + r) * K + k0 + tx] = __float2half_rn(tile[tx][r]);
}

// ---------------- fused QKV bias concat ----------------
__global__ __launch_bounds__(256) void bcat_kernel(
    const float* __restrict__ bq, const float* __restrict__ bk,
    const float* __restrict__ bv, float* __restrict__ outb)
{
    int i = blockIdx.x * 256 + threadIdx.x;
    if (i < NLAYER * 3072) {
        int lyr = i / 3072, c = i % 3072;
        float v = (c < 1024) ? bq[lyr*1024 + c]
                : (c < 2048) ? bk[lyr*1024 + c - 1024]
                             : bv[lyr*1024 + c - 2048];
        outb[i] = v;
    }
}

// ---------------- elementwise 2-plane split (states) ----------------
__global__ __launch_bounds__(256) void esplit_kernel(
    const float* __restrict__ x, __half* __restrict__ h,
    __half* __restrict__ l, int n)
{
    int i = (blockIdx.x * 256 + threadIdx.x) * 4;
    if (i < n) {
        float4 v = *(const float4*)&x[i];
        float a[4] = {v.x, v.y, v.z, v.w};
        __half hh[4], ll[4];
        #pragma unroll
        for (int e = 0; e < 4; e++) split1h(a[e], hh[e], ll[e]);
        __half2 p;
        p.x=hh[0]; p.y=hh[1]; *(__half2*)&h[i]   = p;
        p.x=hh[2]; p.y=hh[3]; *(__half2*)&h[i+2] = p;
        p.x=ll[0]; p.y=ll[1]; *(__half2*)&l[i]   = p;
        p.x=ll[2]; p.y=ll[3]; *(__half2*)&l[i+2] = p;
    }
}

// ---------------- launcher ----------------
extern "C" void kernel_launch(void* const* d_in, const int* in_sizes, int n_in,
                              void* d_out, int out_size) {
    const float* states   = (const float*)d_in[0];
    const int*   actions  = (const int*)d_in[1];
    const int*   tsteps   = (const int*)d_in[2];
    const float* W_se     = (const float*)d_in[3];
    const float* b_se     = (const float*)d_in[4];
    const float* act_tab  = (const float*)d_in[5];
    const float* pos_emb  = (const float*)d_in[6];
    const float* gpe      = (const float*)d_in[7];
    const float* ln1_g    = (const float*)d_in[8];
    const float* ln1_b    = (const float*)d_in[9];
    const float* Wq       = (const float*)d_in[10];
    const float* bq       = (const float*)d_in[11];
    const float* Wk       = (const float*)d_in[12];
    const float* bk       = (const float*)d_in[13];
    const float* Wv       = (const float*)d_in[14];
    const float* bv       = (const float*)d_in[15];
    const float* Wo       = (const float*)d_in[16];
    const float* bo       = (const float*)d_in[17];
    const float* ln2_g    = (const float*)d_in[18];
    const float* ln2_b    = (const float*)d_in[19];
    const float* W1       = (const float*)d_in[20];
    const float* b1       = (const float*)d_in[21];
    const float* W2       = (const float*)d_in[22];
    const float* b2       = (const float*)d_in[23];
    const float* lnf_g    = (const float*)d_in[24];
    const float* lnf_b    = (const float*)d_in[25];
    const float* W_head   = (const float*)d_in[26];
    float* out = (float*)d_out;

    float* F = nullptr;
    cudaGetSymbolAddress((void**)&F, g_f32);
    float* BQKV = nullptr;
    cudaGetSymbolAddress((void**)&BQKV, g_bqkv);
    __half* HP = nullptr;
    cudaGetSymbolAddress((void**)&HP, g_hp);

    float* X  = F;
    float* X2 = X  + N_BLC;
    float* HF = X2 + N_BLC;

    size_t off = 0;
    auto take = [&](size_t n) { __half* p = HP + off; off += n; return p; };
    __half *stH = take(524288), *stL = take(524288);
    __half *wseH = take(131072);
    __half *wAll = take(67108864);
    __half *hdH = take(4194304);
    __half *HbH = take(N_BLC);
    __half *AOH = take(N_BLC);
    __half *MIDH = take(2*N_BLC);
    __half *HFH = take(N_HF);
    __half *QKVH = take(3*N_BLC);

    const int GSM2 = 3*3*5120*2;        // 92160 B
    const int GSM1 = 3*2*5120*2;        // 61440 B
    const int ATSM = 3*4608*2;          // 27648 B
    cudaFuncSetAttribute(gemm_hk<1,true,false,0,2>, cudaFuncAttributeMaxDynamicSharedMemorySize, GSM2);
    cudaFuncSetAttribute(gemm_hk<0,true,false,1,1>, cudaFuncAttributeMaxDynamicSharedMemorySize, GSM1);
    cudaFuncSetAttribute(gemm_hk<0,true,true,0,1>,  cudaFuncAttributeMaxDynamicSharedMemorySize, GSM1);
    cudaFuncSetAttribute(gemm_hk<2,true,false,1,1>, cudaFuncAttributeMaxDynamicSharedMemorySize, GSM1);
    cudaFuncSetAttribute(gemm_hk<0,false,false,0,1>,cudaFuncAttributeMaxDynamicSharedMemorySize, GSM1);
    cudaFuncSetAttribute(attn_kernel, cudaFuncAttributeMaxDynamicSharedMemorySize, ATSM);

    const int Mx = Bb * Lseq;   // 8192
    const int Mh = Bb * Tt;     // 4096
    dim3 thr(256);

    // ---- prep (5 launches before first GEMM so ncu -s 5 profiles gemm_hk) ----
    bcat_kernel<<<96, thr>>>(bq, bk, bv, BQKV);
    esplit_kernel<<<512, thr>>>(states, stH, stL, Mh * Ss);
    wsplit_kernel<<<dim3(Cc/32, Ss/32, 1), thr>>>(W_se, wseH, Ss, Cc, 0, 0);
    wsplit4_kernel<<<dim3(32, 32, 32), thr>>>(Wq, Wk, Wv, Wo, wAll);
    wsplit12_kernel<<<dim3(64, 64, 16), thr>>>(W1, W2, wAll);

    // ---- state encoder + token assembly ----
    gemm_hk<1,true,false,0,2><<<dim3(Cc/128, Mh/128), thr, GSM2>>>(
        stH, stL, wseH, b_se, nullptr, HF, nullptr, nullptr, Mh, Cc, Ss);
    assemble_kernel<<<Mh, thr>>>(HF, actions, tsteps, act_tab, pos_emb, gpe, X);

    for (int lyr = 0; lyr < NLAYER; lyr++) {
        __half* wqkv = wAll + lyr*LWs + OFF_QKVs;
        __half* wo   = wAll + lyr*LWs + OFF_WOs;
        __half* w1   = wAll + lyr*LWs + OFF_W1s;
        __half* w2   = wAll + lyr*LWs + OFF_W2s;

        ln_kernel<<<Mx, thr>>>(X, ln1_g + lyr*Cc, ln1_b + lyr*Cc, HbH, nullptr, 0);
        gemm_hk<0,true,false,1,1><<<dim3(3072/128, Mx/128), thr, GSM1>>>(
            HbH, nullptr, wqkv, BQKV + lyr*3072, nullptr, nullptr, QKVH, nullptr, Mx, 3072, Cc);
        attn_kernel<<<dim3(Lseq/64, Bb*16), dim3(128), ATSM>>>(QKVH, AOH);
        gemm_hk<0,true,true,0,1><<<dim3(Cc/128, Mx/128), thr, GSM1>>>(
            AOH, nullptr, wo, bo + lyr*Cc, X, X2, nullptr, nullptr, Mx, Cc, Cc);
        ln_kernel<<<Mx, thr>>>(X2, ln2_g + lyr*Cc, ln2_b + lyr*Cc, HbH, nullptr, 0);
        gemm_hk<2,true,false,1,1><<<dim3(2*Cc/128, Mx/128), thr, GSM1>>>(
            HbH, nullptr, w1, b1 + lyr*2*Cc, nullptr, nullptr, MIDH, nullptr, Mx, 2*Cc, Cc);
        gemm_hk<0,true,true,0,1><<<dim3(Cc/128, Mx/128), thr, GSM1>>>(
            MIDH, nullptr, w2, b2 + lyr*Cc, X2, X, nullptr, nullptr, Mx, Cc, 2*Cc);
    }

    wsplit_kernel<<<dim3(VOC/32, Cc/32, 1), thr>>>(W_head, hdH, Cc, VOC, 0, 0);
    ln_kernel<<<Mh, thr>>>(X, lnf_g, lnf_b, HFH, nullptr, 1);
    gemm_hk<0,false,false,0,1><<<dim3(VOC/128, Mh/128), thr, GSM1>>>(
        HFH, nullptr, hdH, nullptr, nullptr, out, nullptr, nullptr, Mh, VOC, Cc);
}